// round 2
// baseline (speedup 1.0000x reference)
#include <cuda_runtime.h>
#include <cuda_fp16.h>
#include <cuda_pipeline.h>
#include <mma.h>
#include <cstdint>
using namespace nvcuda;

#define BB 8
#define SS 4096
#define DD 1024
#define NTOK 32768
#define NSMALL 256
#define KSPLIT 3072
#define CHUNK 64
#define NCHUNK 64
#define TOTCHUNK 512

// ---------------- device scratch ----------------
__device__ __half  g_xhi[NTOK * DD];
__device__ __half  g_xlo[NTOK * DD];
__device__ __half  g_wsmall[NSMALL * KSPLIT];
__device__ __half  g_wgate[DD * DD];
__device__ float   g_small[NTOK * NSMALL];
__device__ float   g_glogit[(size_t)NTOK * DD];
__device__ unsigned long long g_tpack[NTOK];
__device__ float   g_c[NTOK * 16];
__device__ float   g_b[NTOK * 16];
__device__ unsigned long long g_Tc[TOTCHUNK];
__device__ float   g_Cc[TOTCHUNK * 16];
__device__ float   g_Bc[TOTCHUNK * 16];
__device__ float   g_hstart[TOTCHUNK * 16];
__device__ float   g_hs[NTOK * 16];
__device__ float   g_sumsq[NTOK];

// ---------------- K0: x -> fp16 hi/lo split ----------------
__global__ void convert_x_kernel(const float* __restrict__ x) {
    int i = blockIdx.x * blockDim.x + threadIdx.x;  // one float4
    float4 v = ((const float4*)x)[i];
    __half h0 = __float2half_rn(v.x), h1 = __float2half_rn(v.y);
    __half h2 = __float2half_rn(v.z), h3 = __float2half_rn(v.w);
    __half l0 = __float2half_rn(v.x - __half2float(h0));
    __half l1 = __float2half_rn(v.y - __half2float(h1));
    __half l2 = __float2half_rn(v.z - __half2float(h2));
    __half l3 = __float2half_rn(v.w - __half2float(h3));
    __half2* hi2 = (__half2*)g_xhi;  __half2* lo2 = (__half2*)g_xlo;
    hi2[i*2+0] = __halves2half2(h0,h1); hi2[i*2+1] = __halves2half2(h2,h3);
    lo2[i*2+0] = __halves2half2(l0,l1); lo2[i*2+1] = __halves2half2(l2,l3);
}

// rows: [0,64) permR |[64,128) permL |[128,144) diagR |[144,160) diagL
//       [160,176) alphaR |[176,192) alphaL |[192,208) W_B |[208,256) zero
// cols: [0,1024)=W_hi (vs x_hi), [1024,2048)=W_lo (vs x_hi), [2048,3072)=W_hi (vs x_lo)
__global__ void convert_wsmall_kernel(const float* __restrict__ wpr, const float* __restrict__ wdr,
                                      const float* __restrict__ war, const float* __restrict__ wpl,
                                      const float* __restrict__ wdl, const float* __restrict__ wal,
                                      const float* __restrict__ wb) {
    int i = blockIdx.x * blockDim.x + threadIdx.x;
    if (i >= NSMALL * KSPLIT) return;
    int n = i / KSPLIT, k = i % KSPLIT;
    const float* src = nullptr;
    if (n < 64)       src = wpr + n * DD;
    else if (n < 128) src = wpl + (n - 64) * DD;
    else if (n < 144) src = wdr + (n - 128) * DD;
    else if (n < 160) src = wdl + (n - 144) * DD;
    else if (n < 176) src = war + (n - 160) * DD;
    else if (n < 192) src = wal + (n - 176) * DD;
    else if (n < 208) src = wb  + (n - 192) * DD;
    __half out = __float2half(0.0f);
    if (src) {
        float w = src[k & 1023];
        __half hi = __float2half_rn(w);
        if (k < 1024)      out = hi;
        else if (k < 2048) out = __float2half_rn(w - __half2float(hi));
        else               out = hi;
    }
    g_wsmall[i] = out;
}

__global__ void convert_wgate_kernel(const float* __restrict__ wg) {
    int i = blockIdx.x * blockDim.x + threadIdx.x;
    if (i < DD * DD) g_wgate[i] = __float2half_rn(wg[i]);
}

// ---------------- GEMM: C[M,N] = A[M,K] * W[N,K]^T ----------------
// BM=128 BN=64 BK=32, 256 thr, 8 warps (4x2), warp tile 32x32
__global__ void __launch_bounds__(256) gemm_kernel(const __half* __restrict__ A0,
                                                   const __half* __restrict__ A1,
                                                   const __half* __restrict__ A2,
                                                   const __half* __restrict__ Bw,
                                                   float* __restrict__ C, int KTOT, int N) {
    __shared__ alignas(16) __half As[2][128][40];
    __shared__ alignas(16) __half Bs[2][64][40];
    const int tid = threadIdx.x, wid = tid >> 5;
    const int wm = wid >> 1, wn = wid & 1;
    const int m0 = blockIdx.y * 128, n0 = blockIdx.x * 64;
    const __half* segs[3] = {A0, A1, A2};

    wmma::fragment<wmma::accumulator, 16, 16, 16, float> acc[2][2];
#pragma unroll
    for (int i = 0; i < 2; i++)
#pragma unroll
        for (int j = 0; j < 2; j++) wmma::fill_fragment(acc[i][j], 0.0f);

    const int NK = KTOT >> 5;
    auto load_stage = [&](int kt, int st) {
        int kbase = kt << 5;
        const __half* Ab = segs[kbase >> 10];
        int koff = kbase & 1023;
#pragma unroll
        for (int r = 0; r < 2; r++) {
            int i = tid + (r << 8);
            int row = i >> 2, cv = i & 3;
            __pipeline_memcpy_async(&As[st][row][cv << 3],
                Ab + (size_t)(m0 + row) * DD + koff + (cv << 3), 16);
        }
        { int row = tid >> 2, cv = tid & 3;
          __pipeline_memcpy_async(&Bs[st][row][cv << 3],
              Bw + (size_t)(n0 + row) * KTOT + kbase + (cv << 3), 16); }
        __pipeline_commit();
    };

    load_stage(0, 0);
    for (int kt = 0; kt < NK; kt++) {
        int st = kt & 1;
        if (kt + 1 < NK) load_stage(kt + 1, st ^ 1);
        __pipeline_wait_prior((kt + 1 < NK) ? 1 : 0);
        __syncthreads();
#pragma unroll
        for (int kk = 0; kk < 2; kk++) {
            wmma::fragment<wmma::matrix_a, 16, 16, 16, __half, wmma::row_major> af[2];
            wmma::fragment<wmma::matrix_b, 16, 16, 16, __half, wmma::col_major> bf[2];
#pragma unroll
            for (int i = 0; i < 2; i++)
                wmma::load_matrix_sync(af[i], &As[st][wm*32 + i*16][kk*16], 40);
#pragma unroll
            for (int j = 0; j < 2; j++)
                wmma::load_matrix_sync(bf[j], &Bs[st][wn*32 + j*16][kk*16], 40);
#pragma unroll
            for (int i = 0; i < 2; i++)
#pragma unroll
                for (int j = 0; j < 2; j++)
                    wmma::mma_sync(acc[i][j], af[i], bf[j], acc[i][j]);
        }
        __syncthreads();
    }
#pragma unroll
    for (int i = 0; i < 2; i++)
#pragma unroll
        for (int j = 0; j < 2; j++)
            wmma::store_matrix_sync(C + (size_t)(m0 + wm*32 + i*16) * N + n0 + wn*32 + j*16,
                                    acc[i][j], N, wmma::mem_row_major);
}

// ---------------- Sinkhorn + argmax + monomial op build ----------------
__device__ __forceinline__ void sinkhorn_argmax(float* a, int* idx) {
#pragma unroll
    for (int it = 0; it < 5; it++) {
#pragma unroll
        for (int i = 0; i < 4; i++) {
            float m = fmaxf(fmaxf(a[i*4], a[i*4+1]), fmaxf(a[i*4+2], a[i*4+3]));
            float s = expf(a[i*4]-m)+expf(a[i*4+1]-m)+expf(a[i*4+2]-m)+expf(a[i*4+3]-m);
            float l = m + logf(s);
            a[i*4]-=l; a[i*4+1]-=l; a[i*4+2]-=l; a[i*4+3]-=l;
        }
#pragma unroll
        for (int j = 0; j < 4; j++) {
            float m = fmaxf(fmaxf(a[j], a[4+j]), fmaxf(a[8+j], a[12+j]));
            float s = expf(a[j]-m)+expf(a[4+j]-m)+expf(a[8+j]-m)+expf(a[12+j]-m);
            float l = m + logf(s);
            a[j]-=l; a[4+j]-=l; a[8+j]-=l; a[12+j]-=l;
        }
    }
#pragma unroll
    for (int j = 0; j < 4; j++) {   // argmax over rows, first-max wins (jnp.argmax)
        int bi = 0; float bv = a[j];
        if (a[4+j]  > bv) { bv = a[4+j];  bi = 1; }
        if (a[8+j]  > bv) { bv = a[8+j];  bi = 2; }
        if (a[12+j] > bv) { bv = a[12+j]; bi = 3; }
        idx[j] = bi;
    }
}

__global__ void factor_kernel(const float* __restrict__ mask) {
    int tok = blockIdx.x * blockDim.x + threadIdx.x;
    if (tok >= NTOK) return;
    const float* so = g_small + (size_t)tok * NSMALL;
    int idxR[16], idxL[16];
    float a[16];
#pragma unroll
    for (int r = 0; r < 4; r++) {
#pragma unroll
        for (int e = 0; e < 16; e++) a[e] = so[r*16+e] * 2.0f;   // /TAU
        int id[4]; sinkhorn_argmax(a, id);
#pragma unroll
        for (int j = 0; j < 4; j++) idxR[r*4+j] = id[j];
    }
#pragma unroll
    for (int r = 0; r < 4; r++) {
#pragma unroll
        for (int e = 0; e < 16; e++) a[e] = so[64+r*16+e] * 2.0f;
        int id[4]; sinkhorn_argmax(a, id);
#pragma unroll
        for (int j = 0; j < 4; j++) idxL[r*4+j] = id[j];
    }
    float dR[16], dL[16];
#pragma unroll
    for (int n = 0; n < 16; n++) {
        dR[n] = (1.0f/(1.0f+expf(-so[160+n]))) * tanhf(so[128+n]);
        dL[n] = (1.0f/(1.0f+expf(-so[176+n]))) * tanhf(so[144+n]);
    }
    float mk = mask[tok];
    unsigned long long tp = 0ull;
#pragma unroll
    for (int j = 0; j < 16; j++) {
        int r = j >> 2, jl = j & 3;
        int i1 = r*4 + idxR[r*4+jl];            // after P_R (col j -> argmax row)
        int i2 = ((i1 & 3) << 2) | (i1 >> 2);   // shuffle (4x4 transpose, self-inverse)
        int i3 = (i2 & ~3) + idxL[(i2 & ~3) + (i2 & 3)];  // after P_L
        tp |= ((unsigned long long)i3) << (4*j);
        g_c[tok*16+j] = dR[i1] * dL[i3];
        g_b[tok*16+j] = so[192+j] * mk;
    }
    g_tpack[tok] = tp;
    g_sumsq[tok] = 0.0f;
}

// ---------------- chunked monomial scan ----------------
__global__ void scanA_kernel() {   // per-chunk operator composition
    int wl = threadIdx.x >> 5, lane = threadIdx.x & 31, l = lane & 15;
    int gw = blockIdx.x * 8 + wl;
    __shared__ float sb[8][16];
    float* S = sb[wl];
    int base = (gw >> 6) * SS + (gw & 63) * CHUNK;
    int T = l; float C = 1.0f, Bv = 0.0f;
    for (int s = 0; s < CHUNK; s++) {
        int tok = base + s;
        unsigned long long tp = g_tpack[tok];
        int tj = (int)((tp >> (4*l)) & 15ull);
        float cj = g_c[tok*16+l], bj = g_b[tok*16+l];
        int   tT = __shfl_sync(0xffffffffu, tj, T);
        float cT = __shfl_sync(0xffffffffu, cj, T);
        if (lane < 16) S[l] = bj;
        __syncwarp();
        if (lane < 16) atomicAdd(&S[tj], cj * Bv);
        __syncwarp();
        if (lane < 16) Bv = S[l];
        __syncwarp();
        T = tT; C *= cT;
    }
    if (lane < 16) { g_Cc[gw*16+l] = C; g_Bc[gw*16+l] = Bv; }
    unsigned long long tpk = 0ull;
    for (int j = 0; j < 16; j++) {
        int v = __shfl_sync(0xffffffffu, T, j);
        tpk |= ((unsigned long long)(v & 15)) << (4*j);
    }
    if (lane == 0) g_Tc[gw] = tpk;
}

__global__ void scanB_kernel() {   // sequential over chunks, 1 warp per batch
    int wl = threadIdx.x >> 5, lane = threadIdx.x & 31, l = lane & 15;
    __shared__ float sb[8][16];
    float* S = sb[wl];
    float h = 0.0f;
    for (int k = 0; k < NCHUNK; k++) {
        int cid = wl * NCHUNK + k;
        if (lane < 16) g_hstart[cid*16+l] = h;
        unsigned long long tp = g_Tc[cid];
        int tj = (int)((tp >> (4*l)) & 15ull);
        float cj = g_Cc[cid*16+l], bj = g_Bc[cid*16+l];
        if (lane < 16) S[l] = bj;
        __syncwarp();
        if (lane < 16) atomicAdd(&S[tj], cj * h);
        __syncwarp();
        if (lane < 16) h = S[l];
        __syncwarp();
    }
}

__global__ void scanC_kernel() {   // replay within chunk, emit h per token
    int wl = threadIdx.x >> 5, lane = threadIdx.x & 31, l = lane & 15;
    int gw = blockIdx.x * 8 + wl;
    __shared__ float sb[8][16];
    float* S = sb[wl];
    int base = (gw >> 6) * SS + (gw & 63) * CHUNK;
    float h = (lane < 16) ? g_hstart[gw*16+l] : 0.0f;
    for (int s = 0; s < CHUNK; s++) {
        int tok = base + s;
        unsigned long long tp = g_tpack[tok];
        int tj = (int)((tp >> (4*l)) & 15ull);
        float cj = g_c[tok*16+l], bj = g_b[tok*16+l];
        if (lane < 16) S[l] = bj;
        __syncwarp();
        if (lane < 16) atomicAdd(&S[tj], cj * h);
        __syncwarp();
        if (lane < 16) { h = S[l]; g_hs[tok*16+l] = h; }
        __syncwarp();
    }
}

// ---------------- output: y = gate * (hs . W_C^T), then RMS ----------------
__global__ void __launch_bounds__(256) out1_kernel(const float* __restrict__ WC,
                                                   float* __restrict__ out) {
    extern __shared__ float sWC[];    // [n][1024] transposed, conflict-free
    __shared__ float sHS[16][16];
    int tid = threadIdx.x;
    int tok0 = blockIdx.x * 16;
    for (int i = tid; i < 16384; i += 256) { int d = i >> 4, n = i & 15; sWC[n*1024+d] = WC[i]; }
    sHS[tid >> 4][tid & 15] = g_hs[(tok0 + (tid >> 4))*16 + (tid & 15)];
    __syncthreads();
    float sq[16];
#pragma unroll
    for (int t = 0; t < 16; t++) sq[t] = 0.0f;
    for (int it = 0; it < 4; it++) {
        int d = it * 256 + tid;
        float wc[16];
#pragma unroll
        for (int n = 0; n < 16; n++) wc[n] = sWC[n*1024 + d];
#pragma unroll
        for (int t = 0; t < 16; t++) {
            float gl = g_glogit[(size_t)(tok0 + t)*1024 + d];
            float gate = 1.0f / (1.0f + __expf(-gl));
            float acc = 0.0f;
#pragma unroll
            for (int n = 0; n < 16; n++) acc += sHS[t][n] * wc[n];
            float y = gate * acc;
            out[(size_t)(tok0 + t)*1024 + d] = y;
            sq[t] += y * y;
        }
    }
#pragma unroll
    for (int t = 0; t < 16; t++) {
        float v = sq[t];
        v += __shfl_down_sync(0xffffffffu, v, 16);
        v += __shfl_down_sync(0xffffffffu, v, 8);
        v += __shfl_down_sync(0xffffffffu, v, 4);
        v += __shfl_down_sync(0xffffffffu, v, 2);
        v += __shfl_down_sync(0xffffffffu, v, 1);
        if ((tid & 31) == 0) atomicAdd(&g_sumsq[tok0 + t], v);
    }
}

__global__ void out2_kernel(float* __restrict__ out, const float* __restrict__ norm_w) {
    int i = blockIdx.x * blockDim.x + threadIdx.x;   // float4 index
    int tok = i >> 8, d4 = i & 255;
    float inv = rsqrtf(g_sumsq[tok] * (1.0f/1024.0f) + 1e-6f);
    float4 v = ((float4*)out)[i];
    float4 w = ((const float4*)norm_w)[d4];
    v.x *= inv * w.x; v.y *= inv * w.y; v.z *= inv * w.z; v.w *= inv * w.w;
    ((float4*)out)[i] = v;
}

// ---------------- launch ----------------
extern "C" void kernel_launch(void* const* d_in, const int* in_sizes, int n_in,
                              void* d_out, int out_size) {
    const float* x    = (const float*)d_in[0];
    const float* mask = (const float*)d_in[1];
    const float* wpr  = (const float*)d_in[2];
    const float* wdr  = (const float*)d_in[3];
    const float* war  = (const float*)d_in[4];
    const float* wpl  = (const float*)d_in[5];
    const float* wdl  = (const float*)d_in[6];
    const float* wal  = (const float*)d_in[7];
    const float* wb   = (const float*)d_in[8];
    const float* wc   = (const float*)d_in[9];
    const float* wg   = (const float*)d_in[10];
    const float* nw   = (const float*)d_in[11];
    float* out = (float*)d_out;

    static bool attr_set = false;
    if (!attr_set) {
        cudaFuncSetAttribute(out1_kernel, cudaFuncAttributeMaxDynamicSharedMemorySize, 65536);
        attr_set = true;
    }

    __half *xhi, *xlo, *wsm, *wgt; float *sm, *gl;
    cudaGetSymbolAddress((void**)&xhi, g_xhi);
    cudaGetSymbolAddress((void**)&xlo, g_xlo);
    cudaGetSymbolAddress((void**)&wsm, g_wsmall);
    cudaGetSymbolAddress((void**)&wgt, g_wgate);
    cudaGetSymbolAddress((void**)&sm,  g_small);
    cudaGetSymbolAddress((void**)&gl,  g_glogit);

    convert_x_kernel<<<NTOK * DD / 4 / 256, 256>>>(x);
    convert_wsmall_kernel<<<NSMALL * KSPLIT / 256, 256>>>(wpr, wdr, war, wpl, wdl, wal, wb);
    convert_wgate_kernel<<<DD * DD / 256, 256>>>(wg);

    dim3 gs(NSMALL / 64, NTOK / 128);
    gemm_kernel<<<gs, 256>>>(xhi, xhi, xlo, wsm, sm, KSPLIT, NSMALL);   // split-precision small GEMM
    dim3 gg(DD / 64, NTOK / 128);
    gemm_kernel<<<gg, 256>>>(xhi, xhi, xhi, wgt, gl, DD, DD);           // gate GEMM (K=1024, seg 0 only)

    factor_kernel<<<NTOK / 256, 256>>>(mask);
    scanA_kernel<<<TOTCHUNK / 8, 256>>>();
    scanB_kernel<<<1, 256>>>();
    scanC_kernel<<<TOTCHUNK / 8, 256>>>();

    out1_kernel<<<NTOK / 16, 256, 65536>>>(wc, out);
    out2_kernel<<<NTOK * DD / 4 / 256, 256>>>(out, nw);
}

// round 3
// speedup vs baseline: 1.4610x; 1.4610x over previous
#include <cuda_runtime.h>
#include <cuda_fp16.h>
#include <cuda_pipeline.h>
#include <mma.h>
#include <cstdint>
using namespace nvcuda;

#define BB 8
#define SS 4096
#define DD 1024
#define NTOK 32768
#define NSMALL 256
#define KSPLIT 3072
#define CHUNK 64
#define NCHUNK 64
#define TOTCHUNK 512

// ---------------- device scratch ----------------
__device__ __half  g_xhi[NTOK * DD];
__device__ __half  g_xlo[NTOK * DD];
__device__ __half  g_wsmall[NSMALL * KSPLIT];
__device__ __half  g_wgate[DD * DD];
__device__ float   g_small[NTOK * NSMALL];
__device__ float   g_glogit[(size_t)NTOK * DD];
__device__ unsigned long long g_tpack[NTOK];
__device__ float   g_c[NTOK * 16];
__device__ float   g_b[NTOK * 16];
__device__ unsigned long long g_Tc[TOTCHUNK];
__device__ float   g_Cc[TOTCHUNK * 16];
__device__ float   g_Bc[TOTCHUNK * 16];
__device__ float   g_hstart[TOTCHUNK * 16];
__device__ float   g_hs[NTOK * 16];

// ---------------- K0: x -> fp16 hi/lo split ----------------
__global__ void convert_x_kernel(const float* __restrict__ x) {
    int i = blockIdx.x * blockDim.x + threadIdx.x;  // one float4
    float4 v = ((const float4*)x)[i];
    __half h0 = __float2half_rn(v.x), h1 = __float2half_rn(v.y);
    __half h2 = __float2half_rn(v.z), h3 = __float2half_rn(v.w);
    __half l0 = __float2half_rn(v.x - __half2float(h0));
    __half l1 = __float2half_rn(v.y - __half2float(h1));
    __half l2 = __float2half_rn(v.z - __half2float(h2));
    __half l3 = __float2half_rn(v.w - __half2float(h3));
    __half2* hi2 = (__half2*)g_xhi;  __half2* lo2 = (__half2*)g_xlo;
    hi2[i*2+0] = __halves2half2(h0,h1); hi2[i*2+1] = __halves2half2(h2,h3);
    lo2[i*2+0] = __halves2half2(l0,l1); lo2[i*2+1] = __halves2half2(l2,l3);
}

// rows: [0,64) permR |[64,128) permL |[128,144) diagR |[144,160) diagL
//       [160,176) alphaR |[176,192) alphaL |[192,208) W_B |[208,256) zero
// cols: [0,1024)=W_hi (vs x_hi), [1024,2048)=W_lo (vs x_hi), [2048,3072)=W_hi (vs x_lo)
__global__ void convert_wsmall_kernel(const float* __restrict__ wpr, const float* __restrict__ wdr,
                                      const float* __restrict__ war, const float* __restrict__ wpl,
                                      const float* __restrict__ wdl, const float* __restrict__ wal,
                                      const float* __restrict__ wb) {
    int i = blockIdx.x * blockDim.x + threadIdx.x;
    if (i >= NSMALL * KSPLIT) return;
    int n = i / KSPLIT, k = i % KSPLIT;
    const float* src = nullptr;
    if (n < 64)       src = wpr + n * DD;
    else if (n < 128) src = wpl + (n - 64) * DD;
    else if (n < 144) src = wdr + (n - 128) * DD;
    else if (n < 160) src = wdl + (n - 144) * DD;
    else if (n < 176) src = war + (n - 160) * DD;
    else if (n < 192) src = wal + (n - 176) * DD;
    else if (n < 208) src = wb  + (n - 192) * DD;
    __half out = __float2half(0.0f);
    if (src) {
        float w = src[k & 1023];
        __half hi = __float2half_rn(w);
        if (k < 1024)      out = hi;
        else if (k < 2048) out = __float2half_rn(w - __half2float(hi));
        else               out = hi;
    }
    g_wsmall[i] = out;
}

__global__ void convert_wgate_kernel(const float* __restrict__ wg) {
    int i = blockIdx.x * blockDim.x + threadIdx.x;
    if (i < DD * DD) g_wgate[i] = __float2half_rn(wg[i]);
}

// ---------------- GEMM: C[M,N] = A[M,K] * W[N,K]^T ----------------
// BM=128 BN=128 BK=32, 3-stage cp.async, 256 thr, 8 warps (4x2), warp tile 32x64
#define GSTAGE 3
#define ABYTES (128 * 40)      // halves per stage per operand
__global__ void __launch_bounds__(256) gemm_kernel(const __half* __restrict__ A0,
                                                   const __half* __restrict__ A1,
                                                   const __half* __restrict__ A2,
                                                   const __half* __restrict__ Bw,
                                                   float* __restrict__ C, int KTOT, int N) {
    extern __shared__ __half sh[];
    __half* As = sh;                         // [3][128][40]
    __half* Bs = sh + GSTAGE * ABYTES;       // [3][128][40]
    const int tid = threadIdx.x, wid = tid >> 5;
    const int wm = wid >> 1, wn = wid & 1;   // wm 0..3 (32 rows), wn 0..1 (64 cols)
    const int m0 = blockIdx.y * 128, n0 = blockIdx.x * 128;
    const __half* segs[3] = {A0, A1, A2};

    wmma::fragment<wmma::accumulator, 16, 16, 16, float> acc[2][4];
#pragma unroll
    for (int i = 0; i < 2; i++)
#pragma unroll
        for (int j = 0; j < 4; j++) wmma::fill_fragment(acc[i][j], 0.0f);

    const int NK = KTOT >> 5;
    const int row = tid >> 2, cv = tid & 3;  // for loads: 4 threads per 32-col row

    auto load_stage = [&](int kt, int st) {
        int kbase = kt << 5;
        const __half* Ab = segs[kbase >> 10];
        int koff = kbase & 1023;
#pragma unroll
        for (int r = 0; r < 2; r++) {        // 256 thr x 2 = 512 chunks of 16B -> 128x32 A
            int i = tid + (r << 8);
            int rw = i >> 2, c = i & 3;
            __pipeline_memcpy_async(&As[st * ABYTES + rw * 40 + (c << 3)],
                Ab + (size_t)(m0 + rw) * DD + koff + (c << 3), 16);
        }
#pragma unroll
        for (int r = 0; r < 2; r++) {        // 128x32 B
            int i = tid + (r << 8);
            int rw = i >> 2, c = i & 3;
            __pipeline_memcpy_async(&Bs[st * ABYTES + rw * 40 + (c << 3)],
                Bw + (size_t)(n0 + rw) * KTOT + kbase + (c << 3), 16);
        }
        __pipeline_commit();
    };

    load_stage(0, 0);
    if (NK > 1) load_stage(1, 1);
    for (int kt = 0; kt < NK; kt++) {
        __pipeline_wait_prior(1);
        __syncthreads();
        if (kt + 2 < NK) load_stage(kt + 2, (kt + 2) % GSTAGE);
        int st = kt % GSTAGE;
#pragma unroll
        for (int kk = 0; kk < 2; kk++) {
            wmma::fragment<wmma::matrix_a, 16, 16, 16, __half, wmma::row_major> af[2];
            wmma::fragment<wmma::matrix_b, 16, 16, 16, __half, wmma::col_major> bf[4];
#pragma unroll
            for (int i = 0; i < 2; i++)
                wmma::load_matrix_sync(af[i], &As[st * ABYTES + (wm*32 + i*16) * 40 + kk*16], 40);
#pragma unroll
            for (int j = 0; j < 4; j++)
                wmma::load_matrix_sync(bf[j], &Bs[st * ABYTES + (wn*64 + j*16) * 40 + kk*16], 40);
#pragma unroll
            for (int i = 0; i < 2; i++)
#pragma unroll
                for (int j = 0; j < 4; j++)
                    wmma::mma_sync(acc[i][j], af[i], bf[j], acc[i][j]);
        }
        __syncthreads();
    }
#pragma unroll
    for (int i = 0; i < 2; i++)
#pragma unroll
        for (int j = 0; j < 4; j++)
            wmma::store_matrix_sync(C + (size_t)(m0 + wm*32 + i*16) * N + n0 + wn*64 + j*16,
                                    acc[i][j], N, wmma::mem_row_major);
}

// ---------------- selection helpers (avoid local-memory spills) ----------------
__device__ __forceinline__ float sel16f(const float* v, int i) {
    float a = (i & 8) ? ((i & 4) ? ((i & 2) ? ((i & 1) ? v[15] : v[14]) : ((i & 1) ? v[13] : v[12]))
                                 : ((i & 2) ? ((i & 1) ? v[11] : v[10]) : ((i & 1) ? v[9]  : v[8])))
                      : ((i & 4) ? ((i & 2) ? ((i & 1) ? v[7]  : v[6])  : ((i & 1) ? v[5]  : v[4]))
                                 : ((i & 2) ? ((i & 1) ? v[3]  : v[2])  : ((i & 1) ? v[1]  : v[0])));
    return a;
}
__device__ __forceinline__ int sel16i(const int* v, int i) {
    int a = (i & 8) ? ((i & 4) ? ((i & 2) ? ((i & 1) ? v[15] : v[14]) : ((i & 1) ? v[13] : v[12]))
                               : ((i & 2) ? ((i & 1) ? v[11] : v[10]) : ((i & 1) ? v[9]  : v[8])))
                    : ((i & 4) ? ((i & 2) ? ((i & 1) ? v[7]  : v[6])  : ((i & 1) ? v[5]  : v[4]))
                               : ((i & 2) ? ((i & 1) ? v[3]  : v[2])  : ((i & 1) ? v[1]  : v[0])));
    return a;
}

// ---------------- Sinkhorn + argmax + monomial op build ----------------
__device__ __forceinline__ void sinkhorn_argmax(float* a, int* idx) {
#pragma unroll
    for (int it = 0; it < 5; it++) {
#pragma unroll
        for (int i = 0; i < 4; i++) {
            float m = fmaxf(fmaxf(a[i*4], a[i*4+1]), fmaxf(a[i*4+2], a[i*4+3]));
            float s = expf(a[i*4]-m)+expf(a[i*4+1]-m)+expf(a[i*4+2]-m)+expf(a[i*4+3]-m);
            float l = m + logf(s);
            a[i*4]-=l; a[i*4+1]-=l; a[i*4+2]-=l; a[i*4+3]-=l;
        }
#pragma unroll
        for (int j = 0; j < 4; j++) {
            float m = fmaxf(fmaxf(a[j], a[4+j]), fmaxf(a[8+j], a[12+j]));
            float s = expf(a[j]-m)+expf(a[4+j]-m)+expf(a[8+j]-m)+expf(a[12+j]-m);
            float l = m + logf(s);
            a[j]-=l; a[4+j]-=l; a[8+j]-=l; a[12+j]-=l;
        }
    }
#pragma unroll
    for (int j = 0; j < 4; j++) {   // argmax over rows, first-max wins (jnp.argmax)
        int bi = 0; float bv = a[j];
        if (a[4+j]  > bv) { bv = a[4+j];  bi = 1; }
        if (a[8+j]  > bv) { bv = a[8+j];  bi = 2; }
        if (a[12+j] > bv) { bv = a[12+j]; bi = 3; }
        idx[j] = bi;
    }
}

__global__ void factor_kernel(const float* __restrict__ mask) {
    int tok = blockIdx.x * blockDim.x + threadIdx.x;
    if (tok >= NTOK) return;
    const float* so = g_small + (size_t)tok * NSMALL;
    int idxR[16], idxL[16];
    float a[16];
#pragma unroll
    for (int r = 0; r < 4; r++) {
#pragma unroll
        for (int e = 0; e < 16; e++) a[e] = so[r*16+e] * 2.0f;   // /TAU
        int id[4]; sinkhorn_argmax(a, id);
#pragma unroll
        for (int j = 0; j < 4; j++) idxR[r*4+j] = id[j];
    }
#pragma unroll
    for (int r = 0; r < 4; r++) {
#pragma unroll
        for (int e = 0; e < 16; e++) a[e] = so[64+r*16+e] * 2.0f;
        int id[4]; sinkhorn_argmax(a, id);
#pragma unroll
        for (int j = 0; j < 4; j++) idxL[r*4+j] = id[j];
    }
    float dR[16], dL[16];
#pragma unroll
    for (int n = 0; n < 16; n++) {
        dR[n] = __fdividef(1.0f, 1.0f + __expf(-so[160+n])) * tanhf(so[128+n]);
        dL[n] = __fdividef(1.0f, 1.0f + __expf(-so[176+n])) * tanhf(so[144+n]);
    }
    float mk = mask[tok];
    unsigned long long tp = 0ull;
#pragma unroll
    for (int j = 0; j < 16; j++) {
        int r = j >> 2;
        int i1 = r*4 + idxR[j];                 // after P_R (col j -> argmax row), static idx
        int i2 = ((i1 & 3) << 2) | (i1 >> 2);   // shuffle (4x4 transpose, self-inverse)
        int i3 = (i2 & ~3) + sel16i(idxL, i2);  // after P_L
        tp |= ((unsigned long long)i3) << (4*j);
        g_c[tok*16+j] = sel16f(dR, i1) * sel16f(dL, i3);
        g_b[tok*16+j] = so[192+j] * mk;
    }
    g_tpack[tok] = tp;
}

// ---------------- chunked monomial scan ----------------
__global__ void scanA_kernel() {   // per-chunk operator composition
    int wl = threadIdx.x >> 5, lane = threadIdx.x & 31, l = lane & 15;
    int gw = blockIdx.x * 8 + wl;
    __shared__ float sb[8][16];
    float* S = sb[wl];
    int base = (gw >> 6) * SS + (gw & 63) * CHUNK;
    int T = l; float C = 1.0f, Bv = 0.0f;
    for (int s = 0; s < CHUNK; s++) {
        int tok = base + s;
        unsigned long long tp = g_tpack[tok];
        int tj = (int)((tp >> (4*l)) & 15ull);
        float cj = g_c[tok*16+l], bj = g_b[tok*16+l];
        int   tT = __shfl_sync(0xffffffffu, tj, T);
        float cT = __shfl_sync(0xffffffffu, cj, T);
        if (lane < 16) S[l] = bj;
        __syncwarp();
        if (lane < 16) atomicAdd(&S[tj], cj * Bv);
        __syncwarp();
        if (lane < 16) Bv = S[l];
        __syncwarp();
        T = tT; C *= cT;
    }
    if (lane < 16) { g_Cc[gw*16+l] = C; g_Bc[gw*16+l] = Bv; }
    unsigned long long tpk = 0ull;
    for (int j = 0; j < 16; j++) {
        int v = __shfl_sync(0xffffffffu, T, j);
        tpk |= ((unsigned long long)(v & 15)) << (4*j);
    }
    if (lane == 0) g_Tc[gw] = tpk;
}

__global__ void scanB_kernel() {   // sequential over chunks, 1 warp per batch
    int wl = threadIdx.x >> 5, lane = threadIdx.x & 31, l = lane & 15;
    __shared__ float sb[8][16];
    float* S = sb[wl];
    float h = 0.0f;
    for (int k = 0; k < NCHUNK; k++) {
        int cid = wl * NCHUNK + k;
        if (lane < 16) g_hstart[cid*16+l] = h;
        unsigned long long tp = g_Tc[cid];
        int tj = (int)((tp >> (4*l)) & 15ull);
        float cj = g_Cc[cid*16+l], bj = g_Bc[cid*16+l];
        if (lane < 16) S[l] = bj;
        __syncwarp();
        if (lane < 16) atomicAdd(&S[tj], cj * h);
        __syncwarp();
        if (lane < 16) h = S[l];
        __syncwarp();
    }
}

__global__ void scanC_kernel() {   // replay within chunk, emit h per token
    int wl = threadIdx.x >> 5, lane = threadIdx.x & 31, l = lane & 15;
    int gw = blockIdx.x * 8 + wl;
    __shared__ float sb[8][16];
    float* S = sb[wl];
    int base = (gw >> 6) * SS + (gw & 63) * CHUNK;
    float h = (lane < 16) ? g_hstart[gw*16+l] : 0.0f;
    for (int s = 0; s < CHUNK; s++) {
        int tok = base + s;
        unsigned long long tp = g_tpack[tok];
        int tj = (int)((tp >> (4*l)) & 15ull);
        float cj = g_c[tok*16+l], bj = g_b[tok*16+l];
        if (lane < 16) S[l] = bj;
        __syncwarp();
        if (lane < 16) atomicAdd(&S[tj], cj * h);
        __syncwarp();
        if (lane < 16) { h = S[l]; g_hs[tok*16+l] = h; }
        __syncwarp();
    }
}

// ---------------- fused output: y = gate * (hs . W_C^T), block-local RMS ----------------
// 16 tokens per block, 256 threads; each thread owns d = it*256+tid for it in 0..3.
// W_C rows cached in registers (no smem conflicts). sumsq reduced in smem, then
// rescale pass rereads y from L2.
__global__ void __launch_bounds__(256) out_kernel(const float* __restrict__ WC,
                                                  const float* __restrict__ norm_w,
                                                  float* __restrict__ out) {
    __shared__ float sHS[16][17];
    __shared__ float ssum[16];
    const int tid = threadIdx.x;
    const int tok0 = blockIdx.x * 16;

    float4 wc4[4][4];   // 4 d's x 16 coeffs
#pragma unroll
    for (int it = 0; it < 4; it++) {
        int d = it * 256 + tid;
        const float4* wr = (const float4*)(WC + (size_t)d * 16);
#pragma unroll
        for (int q = 0; q < 4; q++) wc4[it][q] = wr[q];
    }
    sHS[tid >> 4][tid & 15] = g_hs[(size_t)(tok0 + (tid >> 4)) * 16 + (tid & 15)];
    if (tid < 16) ssum[tid] = 0.0f;
    __syncthreads();

    for (int t = 0; t < 16; t++) {
        float hsr[16];
#pragma unroll
        for (int n = 0; n < 16; n++) hsr[n] = sHS[t][n];
        float local = 0.0f;
#pragma unroll
        for (int it = 0; it < 4; it++) {
            int d = it * 256 + tid;
            size_t off = (size_t)(tok0 + t) * 1024 + d;
            float gl = g_glogit[off];
            float gate = __fdividef(1.0f, 1.0f + __expf(-gl));
            float acc = 0.0f;
#pragma unroll
            for (int q = 0; q < 4; q++) {
                acc = fmaf(hsr[q*4+0], wc4[it][q].x, acc);
                acc = fmaf(hsr[q*4+1], wc4[it][q].y, acc);
                acc = fmaf(hsr[q*4+2], wc4[it][q].z, acc);
                acc = fmaf(hsr[q*4+3], wc4[it][q].w, acc);
            }
            float y = gate * acc;
            out[off] = y;
            local = fmaf(y, y, local);
        }
        local += __shfl_down_sync(0xffffffffu, local, 16);
        local += __shfl_down_sync(0xffffffffu, local, 8);
        local += __shfl_down_sync(0xffffffffu, local, 4);
        local += __shfl_down_sync(0xffffffffu, local, 2);
        local += __shfl_down_sync(0xffffffffu, local, 1);
        if ((tid & 31) == 0) atomicAdd(&ssum[t], local);
    }
    __syncthreads();

    float nw[4];
#pragma unroll
    for (int it = 0; it < 4; it++) nw[it] = norm_w[it * 256 + tid];
#pragma unroll
    for (int t = 0; t < 16; t++) {
        float inv = rsqrtf(ssum[t] * (1.0f / 1024.0f) + 1e-6f);
#pragma unroll
        for (int it = 0; it < 4; it++) {
            size_t off = (size_t)(tok0 + t) * 1024 + it * 256 + tid;
            out[off] = out[off] * inv * nw[it];
        }
    }
}

// ---------------- launch ----------------
extern "C" void kernel_launch(void* const* d_in, const int* in_sizes, int n_in,
                              void* d_out, int out_size) {
    const float* x    = (const float*)d_in[0];
    const float* mask = (const float*)d_in[1];
    const float* wpr  = (const float*)d_in[2];
    const float* wdr  = (const float*)d_in[3];
    const float* war  = (const float*)d_in[4];
    const float* wpl  = (const float*)d_in[5];
    const float* wdl  = (const float*)d_in[6];
    const float* wal  = (const float*)d_in[7];
    const float* wb   = (const float*)d_in[8];
    const float* wc   = (const float*)d_in[9];
    const float* wg   = (const float*)d_in[10];
    const float* nw   = (const float*)d_in[11];
    float* out = (float*)d_out;

    const int gemm_smem = GSTAGE * ABYTES * 2 * (int)sizeof(__half);  // 61440B
    cudaFuncSetAttribute(gemm_kernel, cudaFuncAttributeMaxDynamicSharedMemorySize, gemm_smem);

    __half *xhi, *xlo, *wsm, *wgt; float *sm, *gl;
    cudaGetSymbolAddress((void**)&xhi, g_xhi);
    cudaGetSymbolAddress((void**)&xlo, g_xlo);
    cudaGetSymbolAddress((void**)&wsm, g_wsmall);
    cudaGetSymbolAddress((void**)&wgt, g_wgate);
    cudaGetSymbolAddress((void**)&sm,  g_small);
    cudaGetSymbolAddress((void**)&gl,  g_glogit);

    convert_x_kernel<<<NTOK * DD / 4 / 256, 256>>>(x);
    convert_wsmall_kernel<<<NSMALL * KSPLIT / 256, 256>>>(wpr, wdr, war, wpl, wdl, wal, wb);
    convert_wgate_kernel<<<DD * DD / 256, 256>>>(wg);

    dim3 gs(NSMALL / 128, NTOK / 128);
    gemm_kernel<<<gs, 256, gemm_smem>>>(xhi, xhi, xlo, wsm, sm, KSPLIT, NSMALL);  // split small GEMM
    dim3 gg(DD / 128, NTOK / 128);
    gemm_kernel<<<gg, 256, gemm_smem>>>(xhi, xhi, xhi, wgt, gl, DD, DD);          // gate GEMM

    factor_kernel<<<NTOK / 256, 256>>>(mask);
    scanA_kernel<<<TOTCHUNK / 8, 256>>>();
    scanB_kernel<<<1, 256>>>();
    scanC_kernel<<<TOTCHUNK / 8, 256>>>();

    out_kernel<<<NTOK / 16, 256>>>(wc, nw, out);
}

// round 5
// speedup vs baseline: 1.5869x; 1.0862x over previous
#include <cuda_runtime.h>
#include <cuda_fp16.h>
#include <cuda_pipeline.h>
#include <mma.h>
#include <cstdint>
using namespace nvcuda;

#define BB 8
#define SS 4096
#define DD 1024
#define NTOK 32768
#define NSMALL 256
#define KSPLIT 3072
#define CHUNK 64
#define NCHUNK 64
#define TOTCHUNK 512

// ---------------- device scratch ----------------
__device__ __half  g_xhi[NTOK * DD];
__device__ __half  g_xlo[NTOK * DD];
__device__ __half  g_wsmall[NSMALL * KSPLIT];
__device__ __half  g_wgate[DD * DD];
__device__ float   g_small[NTOK * NSMALL];
__device__ float   g_glogit[(size_t)NTOK * DD];
__device__ unsigned long long g_tpack[NTOK];
__device__ float   g_c[NTOK * 16];
__device__ float   g_b[NTOK * 16];
__device__ unsigned long long g_Tc[TOTCHUNK];
__device__ float   g_Cc[TOTCHUNK * 16];
__device__ float   g_Bc[TOTCHUNK * 16];
__device__ float   g_hstart[TOTCHUNK * 16];
__device__ float   g_hs[NTOK * 16];

// ---------------- K0: x -> fp16 hi/lo split ----------------
__global__ void convert_x_kernel(const float* __restrict__ x) {
    int i = blockIdx.x * blockDim.x + threadIdx.x;  // one float4
    float4 v = ((const float4*)x)[i];
    __half h0 = __float2half_rn(v.x), h1 = __float2half_rn(v.y);
    __half h2 = __float2half_rn(v.z), h3 = __float2half_rn(v.w);
    __half l0 = __float2half_rn(v.x - __half2float(h0));
    __half l1 = __float2half_rn(v.y - __half2float(h1));
    __half l2 = __float2half_rn(v.z - __half2float(h2));
    __half l3 = __float2half_rn(v.w - __half2float(h3));
    __half2* hi2 = (__half2*)g_xhi;  __half2* lo2 = (__half2*)g_xlo;
    hi2[i*2+0] = __halves2half2(h0,h1); hi2[i*2+1] = __halves2half2(h2,h3);
    lo2[i*2+0] = __halves2half2(l0,l1); lo2[i*2+1] = __halves2half2(l2,l3);
}

// rows: [0,64) permR |[64,128) permL |[128,144) diagR |[144,160) diagL
//       [160,176) alphaR |[176,192) alphaL |[192,208) W_B |[208,256) zero
// cols: [0,1024)=W_hi (vs x_hi), [1024,2048)=W_lo (vs x_hi), [2048,3072)=W_hi (vs x_lo)
__global__ void convert_wsmall_kernel(const float* __restrict__ wpr, const float* __restrict__ wdr,
                                      const float* __restrict__ war, const float* __restrict__ wpl,
                                      const float* __restrict__ wdl, const float* __restrict__ wal,
                                      const float* __restrict__ wb) {
    int i = blockIdx.x * blockDim.x + threadIdx.x;
    if (i >= NSMALL * KSPLIT) return;
    int n = i / KSPLIT, k = i % KSPLIT;
    const float* src = nullptr;
    if (n < 64)       src = wpr + n * DD;
    else if (n < 128) src = wpl + (n - 64) * DD;
    else if (n < 144) src = wdr + (n - 128) * DD;
    else if (n < 160) src = wdl + (n - 144) * DD;
    else if (n < 176) src = war + (n - 160) * DD;
    else if (n < 192) src = wal + (n - 176) * DD;
    else if (n < 208) src = wb  + (n - 192) * DD;
    __half out = __float2half(0.0f);
    if (src) {
        float w = src[k & 1023];
        __half hi = __float2half_rn(w);
        if (k < 1024)      out = hi;
        else if (k < 2048) out = __float2half_rn(w - __half2float(hi));
        else               out = hi;
    }
    g_wsmall[i] = out;
}

__global__ void convert_wgate_kernel(const float* __restrict__ wg) {
    int i = blockIdx.x * blockDim.x + threadIdx.x;
    if (i < DD * DD) g_wgate[i] = __float2half_rn(wg[i]);
}

// ---------------- GEMM: C[M,N] = A[M,K] * W[N,K]^T ----------------
// BM=128 BN=256 BK=32, 3-stage cp.async, 512 thr, 16 warps (4x4), warp tile 32x64
#define GSTAGE 3
#define A_H (128 * 40)       // halves per A stage
#define B_H (256 * 40)       // halves per B stage
#define GEMM_SMEM (GSTAGE * (A_H + B_H) * 2)   // 92160 B
__global__ void __launch_bounds__(512) gemm_kernel(const __half* __restrict__ A0,
                                                   const __half* __restrict__ A1,
                                                   const __half* __restrict__ A2,
                                                   const __half* __restrict__ Bw,
                                                   float* __restrict__ C, int KTOT, int N) {
    extern __shared__ __half sh[];
    __half* As = sh;                              // [3][128][40]
    __half* Bs = sh + GSTAGE * A_H;               // [3][256][40]
    const int tid = threadIdx.x, wid = tid >> 5;
    const int wm = wid >> 2, wn = wid & 3;        // 4x4 warps
    const int m0 = blockIdx.y * 128, n0 = blockIdx.x * 256;
    const __half* segs[3] = {A0, A1, A2};

    wmma::fragment<wmma::accumulator, 16, 16, 16, float> acc[2][4];
#pragma unroll
    for (int i = 0; i < 2; i++)
#pragma unroll
        for (int j = 0; j < 4; j++) wmma::fill_fragment(acc[i][j], 0.0f);

    const int NK = KTOT >> 5;

    auto load_stage = [&](int kt, int st) {
        int kbase = kt << 5;
        const __half* Ab = segs[kbase >> 10];
        int koff = kbase & 1023;
        {   // A: 128 rows x 4 chunks of 16B = 512 -> one per thread
            int rw = tid >> 2, c = tid & 3;
            __pipeline_memcpy_async(&As[st * A_H + rw * 40 + (c << 3)],
                Ab + (size_t)(m0 + rw) * DD + koff + (c << 3), 16);
        }
#pragma unroll
        for (int r = 0; r < 2; r++) {   // B: 256 rows x 4 chunks = 1024 -> two per thread
            int i = tid + (r << 9);
            int rw = i >> 2, c = i & 3;
            __pipeline_memcpy_async(&Bs[st * B_H + rw * 40 + (c << 3)],
                Bw + (size_t)(n0 + rw) * KTOT + kbase + (c << 3), 16);
        }
        __pipeline_commit();
    };

    load_stage(0, 0);
    if (NK > 1) load_stage(1, 1);
    for (int kt = 0; kt < NK; kt++) {
        __pipeline_wait_prior(1);
        __syncthreads();
        if (kt + 2 < NK) load_stage(kt + 2, (kt + 2) % GSTAGE);
        int st = kt % GSTAGE;
#pragma unroll
        for (int kk = 0; kk < 2; kk++) {
            wmma::fragment<wmma::matrix_a, 16, 16, 16, __half, wmma::row_major> af[2];
            wmma::fragment<wmma::matrix_b, 16, 16, 16, __half, wmma::col_major> bf[4];
#pragma unroll
            for (int i = 0; i < 2; i++)
                wmma::load_matrix_sync(af[i], &As[st * A_H + (wm*32 + i*16) * 40 + kk*16], 40);
#pragma unroll
            for (int j = 0; j < 4; j++)
                wmma::load_matrix_sync(bf[j], &Bs[st * B_H + (wn*64 + j*16) * 40 + kk*16], 40);
#pragma unroll
            for (int i = 0; i < 2; i++)
#pragma unroll
                for (int j = 0; j < 4; j++)
                    wmma::mma_sync(acc[i][j], af[i], bf[j], acc[i][j]);
        }
        __syncthreads();
    }
#pragma unroll
    for (int i = 0; i < 2; i++)
#pragma unroll
        for (int j = 0; j < 4; j++)
            wmma::store_matrix_sync(C + (size_t)(m0 + wm*32 + i*16) * N + n0 + wn*64 + j*16,
                                    acc[i][j], N, wmma::mem_row_major);
}

// ---------------- selection helpers (avoid local-memory spills) ----------------
__device__ __forceinline__ float sel16f(const float* v, int i) {
    return (i & 8) ? ((i & 4) ? ((i & 2) ? ((i & 1) ? v[15] : v[14]) : ((i & 1) ? v[13] : v[12]))
                              : ((i & 2) ? ((i & 1) ? v[11] : v[10]) : ((i & 1) ? v[9]  : v[8])))
                   : ((i & 4) ? ((i & 2) ? ((i & 1) ? v[7]  : v[6])  : ((i & 1) ? v[5]  : v[4]))
                              : ((i & 2) ? ((i & 1) ? v[3]  : v[2])  : ((i & 1) ? v[1]  : v[0])));
}
__device__ __forceinline__ int sel16i(const int* v, int i) {
    return (i & 8) ? ((i & 4) ? ((i & 2) ? ((i & 1) ? v[15] : v[14]) : ((i & 1) ? v[13] : v[12]))
                              : ((i & 2) ? ((i & 1) ? v[11] : v[10]) : ((i & 1) ? v[9]  : v[8])))
                   : ((i & 4) ? ((i & 2) ? ((i & 1) ? v[7]  : v[6])  : ((i & 1) ? v[5]  : v[4]))
                              : ((i & 2) ? ((i & 1) ? v[3]  : v[2])  : ((i & 1) ? v[1]  : v[0])));
}

// ---------------- Sinkhorn + argmax + monomial op build ----------------
__device__ __forceinline__ void sinkhorn_argmax(float* a, int* idx) {
#pragma unroll
    for (int it = 0; it < 5; it++) {
#pragma unroll
        for (int i = 0; i < 4; i++) {
            float m = fmaxf(fmaxf(a[i*4], a[i*4+1]), fmaxf(a[i*4+2], a[i*4+3]));
            float s = expf(a[i*4]-m)+expf(a[i*4+1]-m)+expf(a[i*4+2]-m)+expf(a[i*4+3]-m);
            float l = m + logf(s);
            a[i*4]-=l; a[i*4+1]-=l; a[i*4+2]-=l; a[i*4+3]-=l;
        }
#pragma unroll
        for (int j = 0; j < 4; j++) {
            float m = fmaxf(fmaxf(a[j], a[4+j]), fmaxf(a[8+j], a[12+j]));
            float s = expf(a[j]-m)+expf(a[4+j]-m)+expf(a[8+j]-m)+expf(a[12+j]-m);
            float l = m + logf(s);
            a[j]-=l; a[4+j]-=l; a[8+j]-=l; a[12+j]-=l;
        }
    }
#pragma unroll
    for (int j = 0; j < 4; j++) {   // argmax over rows, first-max wins (jnp.argmax)
        int bi = 0; float bv = a[j];
        if (a[4+j]  > bv) { bv = a[4+j];  bi = 1; }
        if (a[8+j]  > bv) { bv = a[8+j];  bi = 2; }
        if (a[12+j] > bv) { bv = a[12+j]; bi = 3; }
        idx[j] = bi;
    }
}

__global__ void factor_kernel(const float* __restrict__ mask) {
    int tok = blockIdx.x * blockDim.x + threadIdx.x;
    if (tok >= NTOK) return;
    const float* so = g_small + (size_t)tok * NSMALL;
    int idxR[16], idxL[16];
    float a[16];
#pragma unroll
    for (int r = 0; r < 4; r++) {
#pragma unroll
        for (int e = 0; e < 16; e++) a[e] = so[r*16+e] * 2.0f;   // /TAU
        int id[4]; sinkhorn_argmax(a, id);
#pragma unroll
        for (int j = 0; j < 4; j++) idxR[r*4+j] = id[j];
    }
#pragma unroll
    for (int r = 0; r < 4; r++) {
#pragma unroll
        for (int e = 0; e < 16; e++) a[e] = so[64+r*16+e] * 2.0f;
        int id[4]; sinkhorn_argmax(a, id);
#pragma unroll
        for (int j = 0; j < 4; j++) idxL[r*4+j] = id[j];
    }
    float dR[16], dL[16];
#pragma unroll
    for (int n = 0; n < 16; n++) {
        dR[n] = __fdividef(1.0f, 1.0f + __expf(-so[160+n])) * tanhf(so[128+n]);
        dL[n] = __fdividef(1.0f, 1.0f + __expf(-so[176+n])) * tanhf(so[144+n]);
    }
    float mk = mask[tok];
    unsigned long long tp = 0ull;
#pragma unroll
    for (int j = 0; j < 16; j++) {
        int r = j >> 2;
        int i1 = r*4 + idxR[j];
        int i2 = ((i1 & 3) << 2) | (i1 >> 2);
        int i3 = (i2 & ~3) + sel16i(idxL, i2);
        tp |= ((unsigned long long)i3) << (4*j);
        g_c[tok*16+j] = sel16f(dR, i1) * sel16f(dL, i3);
        g_b[tok*16+j] = so[192+j] * mk;
    }
    g_tpack[tok] = tp;
}

// ---------------- chunked monomial scan ----------------
__global__ void scanA_kernel() {
    int wl = threadIdx.x >> 5, lane = threadIdx.x & 31, l = lane & 15;
    int gw = blockIdx.x * 8 + wl;
    __shared__ float sb[8][16];
    float* S = sb[wl];
    int base = (gw >> 6) * SS + (gw & 63) * CHUNK;
    int T = l; float C = 1.0f, Bv = 0.0f;
    for (int s = 0; s < CHUNK; s++) {
        int tok = base + s;
        unsigned long long tp = g_tpack[tok];
        int tj = (int)((tp >> (4*l)) & 15ull);
        float cj = g_c[tok*16+l], bj = g_b[tok*16+l];
        int   tT = __shfl_sync(0xffffffffu, tj, T);
        float cT = __shfl_sync(0xffffffffu, cj, T);
        if (lane < 16) S[l] = bj;
        __syncwarp();
        if (lane < 16) atomicAdd(&S[tj], cj * Bv);
        __syncwarp();
        if (lane < 16) Bv = S[l];
        __syncwarp();
        T = tT; C *= cT;
    }
    if (lane < 16) { g_Cc[gw*16+l] = C; g_Bc[gw*16+l] = Bv; }
    unsigned long long tpk = 0ull;
    for (int j = 0; j < 16; j++) {
        int v = __shfl_sync(0xffffffffu, T, j);
        tpk |= ((unsigned long long)(v & 15)) << (4*j);
    }
    if (lane == 0) g_Tc[gw] = tpk;
}

__global__ void scanB_kernel() {
    int wl = threadIdx.x >> 5, lane = threadIdx.x & 31, l = lane & 15;
    __shared__ float sb[8][16];
    float* S = sb[wl];
    float h = 0.0f;
    for (int k = 0; k < NCHUNK; k++) {
        int cid = wl * NCHUNK + k;
        if (lane < 16) g_hstart[cid*16+l] = h;
        unsigned long long tp = g_Tc[cid];
        int tj = (int)((tp >> (4*l)) & 15ull);
        float cj = g_Cc[cid*16+l], bj = g_Bc[cid*16+l];
        if (lane < 16) S[l] = bj;
        __syncwarp();
        if (lane < 16) atomicAdd(&S[tj], cj * h);
        __syncwarp();
        if (lane < 16) h = S[l];
        __syncwarp();
    }
}

__global__ void scanC_kernel() {
    int wl = threadIdx.x >> 5, lane = threadIdx.x & 31, l = lane & 15;
    int gw = blockIdx.x * 8 + wl;
    __shared__ float sb[8][16];
    float* S = sb[wl];
    int base = (gw >> 6) * SS + (gw & 63) * CHUNK;
    float h = (lane < 16) ? g_hstart[gw*16+l] : 0.0f;
    for (int s = 0; s < CHUNK; s++) {
        int tok = base + s;
        unsigned long long tp = g_tpack[tok];
        int tj = (int)((tp >> (4*l)) & 15ull);
        float cj = g_c[tok*16+l], bj = g_b[tok*16+l];
        if (lane < 16) S[l] = bj;
        __syncwarp();
        if (lane < 16) atomicAdd(&S[tj], cj * h);
        __syncwarp();
        if (lane < 16) { h = S[l]; g_hs[tok*16+l] = h; }
        __syncwarp();
    }
}

// ---------------- fused output: y = sigmoid(glogit) * (hs . W_C^T), block RMS ----------------
// 16 tokens/block, 256 threads; thread owns 4 CONSECUTIVE d = tid*4..tid*4+3
// -> float4 loads for glogit / out / rescale.
__global__ void __launch_bounds__(256) out_kernel(const float* __restrict__ WC,
                                                  const float* __restrict__ norm_w,
                                                  float* __restrict__ out) {
    __shared__ float sHS[16][17];
    __shared__ float ssum[16];
    const int tid = threadIdx.x;
    const int tok0 = blockIdx.x * 16;
    const int d0 = tid * 4;

    float4 wc4[4][4];   // [q: which d][16 coeffs as 4 float4]
#pragma unroll
    for (int q = 0; q < 4; q++) {
        const float4* wr = (const float4*)(WC + (size_t)(d0 + q) * 16);
#pragma unroll
        for (int p = 0; p < 4; p++) wc4[q][p] = wr[p];
    }
    sHS[tid >> 4][tid & 15] = g_hs[(size_t)(tok0 + (tid >> 4)) * 16 + (tid & 15)];
    if (tid < 16) ssum[tid] = 0.0f;
    __syncthreads();

    for (int t = 0; t < 16; t++) {
        float hsr[16];
#pragma unroll
        for (int n = 0; n < 16; n++) hsr[n] = sHS[t][n];
        size_t off4 = ((size_t)(tok0 + t) * 1024 + d0) >> 2;
        float4 gl4 = ((const float4*)g_glogit)[off4];
        float glv[4] = {gl4.x, gl4.y, gl4.z, gl4.w};
        float4 y4;
        float* yv = (float*)&y4;
        float local = 0.0f;
#pragma unroll
        for (int q = 0; q < 4; q++) {
            float gate = __fdividef(1.0f, 1.0f + __expf(-glv[q]));
            float acc = 0.0f;
#pragma unroll
            for (int p = 0; p < 4; p++) {
                acc = fmaf(hsr[p*4+0], wc4[q][p].x, acc);
                acc = fmaf(hsr[p*4+1], wc4[q][p].y, acc);
                acc = fmaf(hsr[p*4+2], wc4[q][p].z, acc);
                acc = fmaf(hsr[p*4+3], wc4[q][p].w, acc);
            }
            float y = gate * acc;
            yv[q] = y;
            local = fmaf(y, y, local);
        }
        ((float4*)out)[off4] = y4;
        local += __shfl_down_sync(0xffffffffu, local, 16);
        local += __shfl_down_sync(0xffffffffu, local, 8);
        local += __shfl_down_sync(0xffffffffu, local, 4);
        local += __shfl_down_sync(0xffffffffu, local, 2);
        local += __shfl_down_sync(0xffffffffu, local, 1);
        if ((tid & 31) == 0) atomicAdd(&ssum[t], local);
    }
    __syncthreads();

    float4 nw4 = ((const float4*)norm_w)[tid];
#pragma unroll
    for (int t = 0; t < 16; t++) {
        float inv = rsqrtf(ssum[t] * (1.0f / 1024.0f) + 1e-6f);
        size_t off4 = ((size_t)(tok0 + t) * 1024 + d0) >> 2;
        float4 v = ((float4*)out)[off4];
        v.x *= inv * nw4.x; v.y *= inv * nw4.y;
        v.z *= inv * nw4.z; v.w *= inv * nw4.w;
        ((float4*)out)[off4] = v;
    }
}

// ---------------- launch ----------------
extern "C" void kernel_launch(void* const* d_in, const int* in_sizes, int n_in,
                              void* d_out, int out_size) {
    const float* x    = (const float*)d_in[0];
    const float* mask = (const float*)d_in[1];
    const float* wpr  = (const float*)d_in[2];
    const float* wdr  = (const float*)d_in[3];
    const float* war  = (const float*)d_in[4];
    const float* wpl  = (const float*)d_in[5];
    const float* wdl  = (const float*)d_in[6];
    const float* wal  = (const float*)d_in[7];
    const float* wb   = (const float*)d_in[8];
    const float* wc   = (const float*)d_in[9];
    const float* wg   = (const float*)d_in[10];
    const float* nw   = (const float*)d_in[11];
    float* out = (float*)d_out;

    cudaFuncSetAttribute(gemm_kernel, cudaFuncAttributeMaxDynamicSharedMemorySize, GEMM_SMEM);

    __half *xhi, *xlo, *wsm, *wgt; float *sm, *gl;
    cudaGetSymbolAddress((void**)&xhi, g_xhi);
    cudaGetSymbolAddress((void**)&xlo, g_xlo);
    cudaGetSymbolAddress((void**)&wsm, g_wsmall);
    cudaGetSymbolAddress((void**)&wgt, g_wgate);
    cudaGetSymbolAddress((void**)&sm,  g_small);
    cudaGetSymbolAddress((void**)&gl,  g_glogit);

    convert_x_kernel<<<NTOK * DD / 4 / 256, 256>>>(x);
    convert_wsmall_kernel<<<NSMALL * KSPLIT / 256, 256>>>(wpr, wdr, war, wpl, wdl, wal, wb);
    convert_wgate_kernel<<<DD * DD / 256, 256>>>(wg);

    dim3 gs(NSMALL / 256, NTOK / 128);   // (1, 256)
    gemm_kernel<<<gs, 512, GEMM_SMEM>>>(xhi, xhi, xlo, wsm, sm, KSPLIT, NSMALL);
    dim3 gg(DD / 256, NTOK / 128);       // (4, 256)
    gemm_kernel<<<gg, 512, GEMM_SMEM>>>(xhi, xhi, xhi, wgt, gl, DD, DD);

    factor_kernel<<<NTOK / 256, 256>>>(mask);
    scanA_kernel<<<TOTCHUNK / 8, 256>>>();
    scanB_kernel<<<1, 256>>>();
    scanC_kernel<<<TOTCHUNK / 8, 256>>>();

    out_kernel<<<NTOK / 16, 256>>>(wc, nw, out);
}

// round 6
// speedup vs baseline: 1.7555x; 1.1063x over previous
#include <cuda_runtime.h>
#include <cuda_fp16.h>
#include <cuda_pipeline.h>
#include <mma.h>
#include <cstdint>
using namespace nvcuda;

#define BB 8
#define SS 4096
#define DD 1024
#define NTOK 32768
#define NSMALL 256
#define KSPLIT 3072
#define CHUNK 64
#define NCHUNK 64
#define TOTCHUNK 512

// ---------------- device scratch ----------------
__device__ __half  g_xhi[NTOK * DD];
__device__ __half  g_xlo[NTOK * DD];
__device__ __half  g_wsmall[NSMALL * KSPLIT];
__device__ __half  g_wgate[DD * DD];
__device__ float   g_small[NTOK * NSMALL];
__device__ float   g_glogit[(size_t)NTOK * DD];
__device__ unsigned long long g_tpack[NTOK];
__device__ float   g_c[NTOK * 16];
__device__ float   g_b[NTOK * 16];
__device__ unsigned long long g_Tc[TOTCHUNK];
__device__ float   g_Cc[TOTCHUNK * 16];
__device__ float   g_Bc[TOTCHUNK * 16];
__device__ float   g_hstart[TOTCHUNK * 16];
__device__ float   g_hs[NTOK * 16];

// ---------------- K0: x -> fp16 hi/lo split ----------------
__global__ void convert_x_kernel(const float* __restrict__ x) {
    int i = blockIdx.x * blockDim.x + threadIdx.x;  // one float4
    float4 v = ((const float4*)x)[i];
    __half h0 = __float2half_rn(v.x), h1 = __float2half_rn(v.y);
    __half h2 = __float2half_rn(v.z), h3 = __float2half_rn(v.w);
    __half l0 = __float2half_rn(v.x - __half2float(h0));
    __half l1 = __float2half_rn(v.y - __half2float(h1));
    __half l2 = __float2half_rn(v.z - __half2float(h2));
    __half l3 = __float2half_rn(v.w - __half2float(h3));
    __half2* hi2 = (__half2*)g_xhi;  __half2* lo2 = (__half2*)g_xlo;
    hi2[i*2+0] = __halves2half2(h0,h1); hi2[i*2+1] = __halves2half2(h2,h3);
    lo2[i*2+0] = __halves2half2(l0,l1); lo2[i*2+1] = __halves2half2(l2,l3);
}

// rows: [0,64) permR |[64,128) permL |[128,144) diagR |[144,160) diagL
//       [160,176) alphaR |[176,192) alphaL |[192,208) W_B |[208,256) zero
// cols: [0,1024)=W_hi (vs x_hi), [1024,2048)=W_lo (vs x_hi), [2048,3072)=W_hi (vs x_lo)
__global__ void convert_wsmall_kernel(const float* __restrict__ wpr, const float* __restrict__ wdr,
                                      const float* __restrict__ war, const float* __restrict__ wpl,
                                      const float* __restrict__ wdl, const float* __restrict__ wal,
                                      const float* __restrict__ wb) {
    int i = blockIdx.x * blockDim.x + threadIdx.x;
    if (i >= NSMALL * KSPLIT) return;
    int n = i / KSPLIT, k = i % KSPLIT;
    const float* src = nullptr;
    if (n < 64)       src = wpr + n * DD;
    else if (n < 128) src = wpl + (n - 64) * DD;
    else if (n < 144) src = wdr + (n - 128) * DD;
    else if (n < 160) src = wdl + (n - 144) * DD;
    else if (n < 176) src = war + (n - 160) * DD;
    else if (n < 192) src = wal + (n - 176) * DD;
    else if (n < 208) src = wb  + (n - 192) * DD;
    __half out = __float2half(0.0f);
    if (src) {
        float w = src[k & 1023];
        __half hi = __float2half_rn(w);
        if (k < 1024)      out = hi;
        else if (k < 2048) out = __float2half_rn(w - __half2float(hi));
        else               out = hi;
    }
    g_wsmall[i] = out;
}

__global__ void convert_wgate_kernel(const float* __restrict__ wg) {
    int i = blockIdx.x * blockDim.x + threadIdx.x;
    if (i < DD * DD) g_wgate[i] = __float2half_rn(wg[i]);
}

// ---------------- unified GEMM: C[M,N] = A[M,K] * W[N,K]^T ----------------
// BM=128 BN=256 BK=32, 4-stage cp.async, 512 thr, 16 warps (4x4), warp tile 32x64.
// grid (5, 256): bx==0 -> small GEMM (K=3072, split-A segs, out g_small fp32)
//                bx>=1 -> gate GEMM (K=1024, all xhi, out g_glogit, n0=(bx-1)*256)
#define GSTAGE 4
#define A_H (128 * 40)
#define B_H (256 * 40)
#define GEMM_SMEM (GSTAGE * (A_H + B_H) * 2)   // 122880 B
__global__ void __launch_bounds__(512) gemm_kernel(const __half* __restrict__ xhi,
                                                   const __half* __restrict__ xlo,
                                                   const __half* __restrict__ wsm,
                                                   const __half* __restrict__ wgt,
                                                   float* __restrict__ Csm,
                                                   float* __restrict__ Cgl) {
    extern __shared__ __half sh[];
    __half* As = sh;                              // [4][128][40]
    __half* Bs = sh + GSTAGE * A_H;               // [4][256][40]
    const int tid = threadIdx.x, wid = tid >> 5;
    const int wm = wid >> 2, wn = wid & 3;        // 4x4 warps
    const int m0 = blockIdx.y * 128;
    const bool is_small = (blockIdx.x == 0);
    const int n0 = is_small ? 0 : (blockIdx.x - 1) * 256;
    const int KTOT = is_small ? KSPLIT : DD;
    const int N = is_small ? NSMALL : DD;
    const __half* Bw = is_small ? wsm : wgt;
    float* C = is_small ? Csm : Cgl;
    const __half* segs[3];
    segs[0] = xhi; segs[1] = is_small ? xhi : xhi; segs[2] = is_small ? xlo : xhi;

    wmma::fragment<wmma::accumulator, 16, 16, 16, float> acc[2][4];
#pragma unroll
    for (int i = 0; i < 2; i++)
#pragma unroll
        for (int j = 0; j < 4; j++) wmma::fill_fragment(acc[i][j], 0.0f);

    const int NK = KTOT >> 5;

    auto load_stage = [&](int kt, int st) {
        int kbase = kt << 5;
        const __half* Ab = segs[kbase >> 10];
        int koff = kbase & 1023;
        {   // A: 128 rows x 4 chunks of 16B = 512 -> one per thread
            int rw = tid >> 2, c = tid & 3;
            __pipeline_memcpy_async(&As[st * A_H + rw * 40 + (c << 3)],
                Ab + (size_t)(m0 + rw) * DD + koff + (c << 3), 16);
        }
#pragma unroll
        for (int r = 0; r < 2; r++) {   // B: 256 rows x 4 chunks = 1024 -> two per thread
            int i = tid + (r << 9);
            int rw = i >> 2, c = i & 3;
            __pipeline_memcpy_async(&Bs[st * B_H + rw * 40 + (c << 3)],
                Bw + (size_t)(n0 + rw) * KTOT + kbase + (c << 3), 16);
        }
        __pipeline_commit();
    };

    load_stage(0, 0);
    load_stage(1, 1);
    load_stage(2, 2);
    for (int kt = 0; kt < NK; kt++) {
        // exact tail wait: ensure group kt is complete
        if (kt < NK - 2)      __pipeline_wait_prior(2);
        else if (kt == NK - 2) __pipeline_wait_prior(1);
        else                   __pipeline_wait_prior(0);
        __syncthreads();
        if (kt + 3 < NK) load_stage(kt + 3, (kt + 3) & 3);
        int st = kt & 3;
#pragma unroll
        for (int kk = 0; kk < 2; kk++) {
            wmma::fragment<wmma::matrix_a, 16, 16, 16, __half, wmma::row_major> af[2];
            wmma::fragment<wmma::matrix_b, 16, 16, 16, __half, wmma::col_major> bf[4];
#pragma unroll
            for (int i = 0; i < 2; i++)
                wmma::load_matrix_sync(af[i], &As[st * A_H + (wm*32 + i*16) * 40 + kk*16], 40);
#pragma unroll
            for (int j = 0; j < 4; j++)
                wmma::load_matrix_sync(bf[j], &Bs[st * B_H + (wn*64 + j*16) * 40 + kk*16], 40);
#pragma unroll
            for (int i = 0; i < 2; i++)
#pragma unroll
                for (int j = 0; j < 4; j++)
                    wmma::mma_sync(acc[i][j], af[i], bf[j], acc[i][j]);
        }
        // no bottom barrier: next iteration's top barrier protects stage reuse
    }
#pragma unroll
    for (int i = 0; i < 2; i++)
#pragma unroll
        for (int j = 0; j < 4; j++)
            wmma::store_matrix_sync(C + (size_t)(m0 + wm*32 + i*16) * N + n0 + wn*64 + j*16,
                                    acc[i][j], N, wmma::mem_row_major);
}

// ---------------- selection helpers (avoid local-memory spills) ----------------
__device__ __forceinline__ float sel16f(const float* v, int i) {
    return (i & 8) ? ((i & 4) ? ((i & 2) ? ((i & 1) ? v[15] : v[14]) : ((i & 1) ? v[13] : v[12]))
                              : ((i & 2) ? ((i & 1) ? v[11] : v[10]) : ((i & 1) ? v[9]  : v[8])))
                   : ((i & 4) ? ((i & 2) ? ((i & 1) ? v[7]  : v[6])  : ((i & 1) ? v[5]  : v[4]))
                              : ((i & 2) ? ((i & 1) ? v[3]  : v[2])  : ((i & 1) ? v[1]  : v[0])));
}
__device__ __forceinline__ int sel16i(const int* v, int i) {
    return (i & 8) ? ((i & 4) ? ((i & 2) ? ((i & 1) ? v[15] : v[14]) : ((i & 1) ? v[13] : v[12]))
                              : ((i & 2) ? ((i & 1) ? v[11] : v[10]) : ((i & 1) ? v[9]  : v[8])))
                   : ((i & 4) ? ((i & 2) ? ((i & 1) ? v[7]  : v[6])  : ((i & 1) ? v[5]  : v[4]))
                              : ((i & 2) ? ((i & 1) ? v[3]  : v[2])  : ((i & 1) ? v[1]  : v[0])));
}

// ---------------- linear-domain Sinkhorn + argmax ----------------
// p holds exp(logits/TAU). Alternating row/col normalization is exactly the
// exp of the reference's log-domain iteration. Final column pass is skipped:
// it scales each column by a positive constant, never changing the row-argmax.
__device__ __forceinline__ void sinkhorn_argmax_lin(float* p, int* idx) {
#pragma unroll
    for (int it = 0; it < 5; it++) {
#pragma unroll
        for (int i = 0; i < 4; i++) {
            float s = p[i*4] + p[i*4+1] + p[i*4+2] + p[i*4+3];
            float r = __fdividef(1.0f, s);
            p[i*4] *= r; p[i*4+1] *= r; p[i*4+2] *= r; p[i*4+3] *= r;
        }
        if (it < 4) {
#pragma unroll
            for (int j = 0; j < 4; j++) {
                float s = p[j] + p[4+j] + p[8+j] + p[12+j];
                float r = __fdividef(1.0f, s);
                p[j] *= r; p[4+j] *= r; p[8+j] *= r; p[12+j] *= r;
            }
        }
    }
#pragma unroll
    for (int j = 0; j < 4; j++) {   // argmax over rows, first-max wins
        int bi = 0; float bv = p[j];
        if (p[4+j]  > bv) { bv = p[4+j];  bi = 1; }
        if (p[8+j]  > bv) { bv = p[8+j];  bi = 2; }
        if (p[12+j] > bv) { bv = p[12+j]; bi = 3; }
        idx[j] = bi;
    }
}

__global__ void factor_kernel(const float* __restrict__ mask) {
    int tok = blockIdx.x * blockDim.x + threadIdx.x;
    if (tok >= NTOK) return;
    const float* so = g_small + (size_t)tok * NSMALL;
    int idxR[16], idxL[16];
    float a[16];
#pragma unroll
    for (int r = 0; r < 4; r++) {
#pragma unroll
        for (int e = 0; e < 16; e++) a[e] = __expf(so[r*16+e] * 2.0f);   // /TAU
        int id[4]; sinkhorn_argmax_lin(a, id);
#pragma unroll
        for (int j = 0; j < 4; j++) idxR[r*4+j] = id[j];
    }
#pragma unroll
    for (int r = 0; r < 4; r++) {
#pragma unroll
        for (int e = 0; e < 16; e++) a[e] = __expf(so[64+r*16+e] * 2.0f);
        int id[4]; sinkhorn_argmax_lin(a, id);
#pragma unroll
        for (int j = 0; j < 4; j++) idxL[r*4+j] = id[j];
    }
    float dR[16], dL[16];
#pragma unroll
    for (int n = 0; n < 16; n++) {
        dR[n] = __fdividef(1.0f, 1.0f + __expf(-so[160+n])) * tanhf(so[128+n]);
        dL[n] = __fdividef(1.0f, 1.0f + __expf(-so[176+n])) * tanhf(so[144+n]);
    }
    float mk = mask[tok];
    unsigned long long tp = 0ull;
#pragma unroll
    for (int j = 0; j < 16; j++) {
        int r = j >> 2;
        int i1 = r*4 + idxR[j];
        int i2 = ((i1 & 3) << 2) | (i1 >> 2);
        int i3 = (i2 & ~3) + sel16i(idxL, i2);
        tp |= ((unsigned long long)i3) << (4*j);
        g_c[tok*16+j] = sel16f(dR, i1) * sel16f(dL, i3);
        g_b[tok*16+j] = so[192+j] * mk;
    }
    g_tpack[tok] = tp;
}

// ---------------- chunked monomial scan ----------------
__global__ void scanA_kernel() {
    int wl = threadIdx.x >> 5, lane = threadIdx.x & 31, l = lane & 15;
    int gw = blockIdx.x * 8 + wl;
    __shared__ float sb[8][16];
    float* S = sb[wl];
    int base = (gw >> 6) * SS + (gw & 63) * CHUNK;
    int T = l; float C = 1.0f, Bv = 0.0f;
    for (int s = 0; s < CHUNK; s++) {
        int tok = base + s;
        unsigned long long tp = g_tpack[tok];
        int tj = (int)((tp >> (4*l)) & 15ull);
        float cj = g_c[tok*16+l], bj = g_b[tok*16+l];
        int   tT = __shfl_sync(0xffffffffu, tj, T);
        float cT = __shfl_sync(0xffffffffu, cj, T);
        if (lane < 16) S[l] = bj;
        __syncwarp();
        if (lane < 16) atomicAdd(&S[tj], cj * Bv);
        __syncwarp();
        if (lane < 16) Bv = S[l];
        __syncwarp();
        T = tT; C *= cT;
    }
    if (lane < 16) { g_Cc[gw*16+l] = C; g_Bc[gw*16+l] = Bv; }
    unsigned long long tpk = 0ull;
    for (int j = 0; j < 16; j++) {
        int v = __shfl_sync(0xffffffffu, T, j);
        tpk |= ((unsigned long long)(v & 15)) << (4*j);
    }
    if (lane == 0) g_Tc[gw] = tpk;
}

__global__ void scanB_kernel() {
    int wl = threadIdx.x >> 5, lane = threadIdx.x & 31, l = lane & 15;
    __shared__ float sb[8][16];
    float* S = sb[wl];
    float h = 0.0f;
    for (int k = 0; k < NCHUNK; k++) {
        int cid = wl * NCHUNK + k;
        if (lane < 16) g_hstart[cid*16+l] = h;
        unsigned long long tp = g_Tc[cid];
        int tj = (int)((tp >> (4*l)) & 15ull);
        float cj = g_Cc[cid*16+l], bj = g_Bc[cid*16+l];
        if (lane < 16) S[l] = bj;
        __syncwarp();
        if (lane < 16) atomicAdd(&S[tj], cj * h);
        __syncwarp();
        if (lane < 16) h = S[l];
        __syncwarp();
    }
}

__global__ void scanC_kernel() {
    int wl = threadIdx.x >> 5, lane = threadIdx.x & 31, l = lane & 15;
    int gw = blockIdx.x * 8 + wl;
    __shared__ float sb[8][16];
    float* S = sb[wl];
    int base = (gw >> 6) * SS + (gw & 63) * CHUNK;
    float h = (lane < 16) ? g_hstart[gw*16+l] : 0.0f;
    for (int s = 0; s < CHUNK; s++) {
        int tok = base + s;
        unsigned long long tp = g_tpack[tok];
        int tj = (int)((tp >> (4*l)) & 15ull);
        float cj = g_c[tok*16+l], bj = g_b[tok*16+l];
        if (lane < 16) S[l] = bj;
        __syncwarp();
        if (lane < 16) atomicAdd(&S[tj], cj * h);
        __syncwarp();
        if (lane < 16) { h = S[l]; g_hs[tok*16+l] = h; }
        __syncwarp();
    }
}

// ---------------- fused output: y = sigmoid(glogit) * (hs . W_C^T), block RMS ----------------
__global__ void __launch_bounds__(256) out_kernel(const float* __restrict__ WC,
                                                  const float* __restrict__ norm_w,
                                                  float* __restrict__ out) {
    __shared__ float sHS[16][17];
    __shared__ float ssum[16];
    const int tid = threadIdx.x;
    const int tok0 = blockIdx.x * 16;
    const int d0 = tid * 4;

    float4 wc4[4][4];
#pragma unroll
    for (int q = 0; q < 4; q++) {
        const float4* wr = (const float4*)(WC + (size_t)(d0 + q) * 16);
#pragma unroll
        for (int p = 0; p < 4; p++) wc4[q][p] = wr[p];
    }
    sHS[tid >> 4][tid & 15] = g_hs[(size_t)(tok0 + (tid >> 4)) * 16 + (tid & 15)];
    if (tid < 16) ssum[tid] = 0.0f;
    __syncthreads();

    for (int t = 0; t < 16; t++) {
        float hsr[16];
#pragma unroll
        for (int n = 0; n < 16; n++) hsr[n] = sHS[t][n];
        size_t off4 = ((size_t)(tok0 + t) * 1024 + d0) >> 2;
        float4 gl4 = ((const float4*)g_glogit)[off4];
        float glv[4] = {gl4.x, gl4.y, gl4.z, gl4.w};
        float4 y4;
        float* yv = (float*)&y4;
        float local = 0.0f;
#pragma unroll
        for (int q = 0; q < 4; q++) {
            float gate = __fdividef(1.0f, 1.0f + __expf(-glv[q]));
            float acc = 0.0f;
#pragma unroll
            for (int p = 0; p < 4; p++) {
                acc = fmaf(hsr[p*4+0], wc4[q][p].x, acc);
                acc = fmaf(hsr[p*4+1], wc4[q][p].y, acc);
                acc = fmaf(hsr[p*4+2], wc4[q][p].z, acc);
                acc = fmaf(hsr[p*4+3], wc4[q][p].w, acc);
            }
            float y = gate * acc;
            yv[q] = y;
            local = fmaf(y, y, local);
        }
        ((float4*)out)[off4] = y4;
        local += __shfl_down_sync(0xffffffffu, local, 16);
        local += __shfl_down_sync(0xffffffffu, local, 8);
        local += __shfl_down_sync(0xffffffffu, local, 4);
        local += __shfl_down_sync(0xffffffffu, local, 2);
        local += __shfl_down_sync(0xffffffffu, local, 1);
        if ((tid & 31) == 0) atomicAdd(&ssum[t], local);
    }
    __syncthreads();

    float4 nw4 = ((const float4*)norm_w)[tid];
#pragma unroll
    for (int t = 0; t < 16; t++) {
        float inv = rsqrtf(ssum[t] * (1.0f / 1024.0f) + 1e-6f);
        size_t off4 = ((size_t)(tok0 + t) * 1024 + d0) >> 2;
        float4 v = ((float4*)out)[off4];
        v.x *= inv * nw4.x; v.y *= inv * nw4.y;
        v.z *= inv * nw4.z; v.w *= inv * nw4.w;
        ((float4*)out)[off4] = v;
    }
}

// ---------------- launch ----------------
extern "C" void kernel_launch(void* const* d_in, const int* in_sizes, int n_in,
                              void* d_out, int out_size) {
    const float* x    = (const float*)d_in[0];
    const float* mask = (const float*)d_in[1];
    const float* wpr  = (const float*)d_in[2];
    const float* wdr  = (const float*)d_in[3];
    const float* war  = (const float*)d_in[4];
    const float* wpl  = (const float*)d_in[5];
    const float* wdl  = (const float*)d_in[6];
    const float* wal  = (const float*)d_in[7];
    const float* wb   = (const float*)d_in[8];
    const float* wc   = (const float*)d_in[9];
    const float* wg   = (const float*)d_in[10];
    const float* nw   = (const float*)d_in[11];
    float* out = (float*)d_out;

    cudaFuncSetAttribute(gemm_kernel, cudaFuncAttributeMaxDynamicSharedMemorySize, GEMM_SMEM);

    __half *xhi, *xlo, *wsm, *wgt; float *sm, *gl;
    cudaGetSymbolAddress((void**)&xhi, g_xhi);
    cudaGetSymbolAddress((void**)&xlo, g_xlo);
    cudaGetSymbolAddress((void**)&wsm, g_wsmall);
    cudaGetSymbolAddress((void**)&wgt, g_wgate);
    cudaGetSymbolAddress((void**)&sm,  g_small);
    cudaGetSymbolAddress((void**)&gl,  g_glogit);

    convert_x_kernel<<<NTOK * DD / 4 / 256, 256>>>(x);
    convert_wsmall_kernel<<<NSMALL * KSPLIT / 256, 256>>>(wpr, wdr, war, wpl, wdl, wal, wb);
    convert_wgate_kernel<<<DD * DD / 256, 256>>>(wg);

    dim3 gall(5, NTOK / 128);    // bx=0: small GEMM; bx=1..4: gate GEMM
    gemm_kernel<<<gall, 512, GEMM_SMEM>>>(xhi, xlo, wsm, wgt, sm, gl);

    factor_kernel<<<NTOK / 256, 256>>>(mask);
    scanA_kernel<<<TOTCHUNK / 8, 256>>>();
    scanB_kernel<<<1, 256>>>();
    scanC_kernel<<<TOTCHUNK / 8, 256>>>();

    out_kernel<<<NTOK / 16, 256>>>(wc, nw, out);
}

// round 7
// speedup vs baseline: 2.0724x; 1.1805x over previous
#include <cuda_runtime.h>
#include <cuda_fp16.h>
#include <cuda_pipeline.h>
#include <mma.h>
#include <cstdint>
using namespace nvcuda;

#define BB 8
#define SS 4096
#define DD 1024
#define NTOK 32768
#define NSMALL 256
#define KSPLIT 3072
#define CHUNK 64
#define NCHUNK 64
#define TOTCHUNK 512

// ---------------- device scratch ----------------
__device__ __half  g_xhi[NTOK * DD];
__device__ __half  g_xlo[NTOK * DD];
__device__ __half  g_wsmall[NSMALL * KSPLIT];
__device__ __half  g_wgate[DD * DD];
__device__ float   g_small[NTOK * NSMALL];
__device__ float   g_glogit[(size_t)NTOK * DD];
__device__ unsigned long long g_tpack[NTOK];
__device__ float   g_c[NTOK * 16];
__device__ float   g_b[NTOK * 16];
__device__ unsigned long long g_Tc[TOTCHUNK];
__device__ float   g_Cc[TOTCHUNK * 16];
__device__ float   g_Bc[TOTCHUNK * 16];
__device__ float   g_hstart[TOTCHUNK * 16];
__device__ float   g_hs[NTOK * 16];

// ---------------- K0: x -> fp16 hi/lo split ----------------
__global__ void convert_x_kernel(const float* __restrict__ x) {
    int i = blockIdx.x * blockDim.x + threadIdx.x;  // one float4
    float4 v = ((const float4*)x)[i];
    __half h0 = __float2half_rn(v.x), h1 = __float2half_rn(v.y);
    __half h2 = __float2half_rn(v.z), h3 = __float2half_rn(v.w);
    __half l0 = __float2half_rn(v.x - __half2float(h0));
    __half l1 = __float2half_rn(v.y - __half2float(h1));
    __half l2 = __float2half_rn(v.z - __half2float(h2));
    __half l3 = __float2half_rn(v.w - __half2float(h3));
    __half2* hi2 = (__half2*)g_xhi;  __half2* lo2 = (__half2*)g_xlo;
    hi2[i*2+0] = __halves2half2(h0,h1); hi2[i*2+1] = __halves2half2(h2,h3);
    lo2[i*2+0] = __halves2half2(l0,l1); lo2[i*2+1] = __halves2half2(l2,l3);
}

// rows: [0,64) permR |[64,128) permL |[128,144) diagR |[144,160) diagL
//       [160,176) alphaR |[176,192) alphaL |[192,208) W_B |[208,256) zero
// cols: [0,1024)=W_hi (vs x_hi), [1024,2048)=W_lo (vs x_hi), [2048,3072)=W_hi (vs x_lo)
__global__ void convert_wsmall_kernel(const float* __restrict__ wpr, const float* __restrict__ wdr,
                                      const float* __restrict__ war, const float* __restrict__ wpl,
                                      const float* __restrict__ wdl, const float* __restrict__ wal,
                                      const float* __restrict__ wb) {
    int i = blockIdx.x * blockDim.x + threadIdx.x;
    if (i >= NSMALL * KSPLIT) return;
    int n = i / KSPLIT, k = i % KSPLIT;
    const float* src = nullptr;
    if (n < 64)       src = wpr + n * DD;
    else if (n < 128) src = wpl + (n - 64) * DD;
    else if (n < 144) src = wdr + (n - 128) * DD;
    else if (n < 160) src = wdl + (n - 144) * DD;
    else if (n < 176) src = war + (n - 160) * DD;
    else if (n < 192) src = wal + (n - 176) * DD;
    else if (n < 208) src = wb  + (n - 192) * DD;
    __half out = __float2half(0.0f);
    if (src) {
        float w = src[k & 1023];
        __half hi = __float2half_rn(w);
        if (k < 1024)      out = hi;
        else if (k < 2048) out = __float2half_rn(w - __half2float(hi));
        else               out = hi;
    }
    g_wsmall[i] = out;
}

__global__ void convert_wgate_kernel(const float* __restrict__ wg) {
    int i = blockIdx.x * blockDim.x + threadIdx.x;
    if (i < DD * DD) g_wgate[i] = __float2half_rn(wg[i]);
}

// ---------------- unified GEMM: C[M,N] = A[M,K] * W[N,K]^T ----------------
// BM=128 BN=128 BK=64, 2-stage cp.async, 256 thr, 8 warps (4x2), warp tile 32x64.
// 2 CTAs/SM (smem 73.7KB, regs<=128). grid (10, 256):
//   bx<2  -> small GEMM (K=3072, split-A segs, out g_small, n0=bx*128)
//   bx>=2 -> gate GEMM (K=1024, all xhi, out g_glogit, n0=(bx-2)*128)
#define BKH 64
#define LDH 72                      // row stride in halves (144B, conflict-free ldsm)
#define STG_H (128 * LDH)           // halves per operand per stage
#define GEMM_SMEM (2 * STG_H * 2 * 2)   // 73728 B
__global__ void __launch_bounds__(256, 2) gemm_kernel(const __half* __restrict__ xhi,
                                                      const __half* __restrict__ xlo,
                                                      const __half* __restrict__ wsm,
                                                      const __half* __restrict__ wgt,
                                                      float* __restrict__ Csm,
                                                      float* __restrict__ Cgl) {
    extern __shared__ __half sh[];
    __half* As = sh;                 // [2][128][72]
    __half* Bs = sh + 2 * STG_H;     // [2][128][72]
    const int tid = threadIdx.x, wid = tid >> 5;
    const int wm = wid >> 1, wn = wid & 1;    // 4x2 warps, warp tile 32x64
    const int m0 = blockIdx.y * 128;
    const bool is_small = (blockIdx.x < 2);
    const int n0 = is_small ? blockIdx.x * 128 : (blockIdx.x - 2) * 128;
    const int KTOT = is_small ? KSPLIT : DD;
    const int N = is_small ? NSMALL : DD;
    const __half* Bw = is_small ? wsm : wgt;
    float* C = is_small ? Csm : Cgl;
    const __half* segs[3];
    segs[0] = xhi; segs[1] = xhi; segs[2] = is_small ? xlo : xhi;

    wmma::fragment<wmma::accumulator, 16, 16, 16, float> acc[2][4];
#pragma unroll
    for (int i = 0; i < 2; i++)
#pragma unroll
        for (int j = 0; j < 4; j++) wmma::fill_fragment(acc[i][j], 0.0f);

    const int NK = KTOT / BKH;

    auto load_stage = [&](int kt, int st) {
        int kbase = kt * BKH;
        const __half* Ab = segs[kbase >> 10];
        int koff = kbase & 1023;
        // A: 128 rows x 8 chunks of 16B = 1024 chunks; 256 thr x 4
#pragma unroll
        for (int r = 0; r < 4; r++) {
            int i = tid + (r << 8);
            int rw = i >> 3, c = i & 7;
            __pipeline_memcpy_async(&As[st * STG_H + rw * LDH + (c << 3)],
                Ab + (size_t)(m0 + rw) * DD + koff + (c << 3), 16);
        }
#pragma unroll
        for (int r = 0; r < 4; r++) {
            int i = tid + (r << 8);
            int rw = i >> 3, c = i & 7;
            __pipeline_memcpy_async(&Bs[st * STG_H + rw * LDH + (c << 3)],
                Bw + (size_t)(n0 + rw) * KTOT + kbase + (c << 3), 16);
        }
        __pipeline_commit();
    };

    load_stage(0, 0);
    for (int kt = 0; kt < NK; kt++) {
        __pipeline_wait_prior(0);    // only load(kt) in flight -> it is complete
        __syncthreads();             // all warps done computing stage kt-1
        if (kt + 1 < NK) load_stage(kt + 1, (kt + 1) & 1);
        int st = kt & 1;
#pragma unroll
        for (int kk = 0; kk < 4; kk++) {
            wmma::fragment<wmma::matrix_a, 16, 16, 16, __half, wmma::row_major> af[2];
            wmma::fragment<wmma::matrix_b, 16, 16, 16, __half, wmma::col_major> bf[4];
#pragma unroll
            for (int i = 0; i < 2; i++)
                wmma::load_matrix_sync(af[i], &As[st * STG_H + (wm*32 + i*16) * LDH + kk*16], LDH);
#pragma unroll
            for (int j = 0; j < 4; j++)
                wmma::load_matrix_sync(bf[j], &Bs[st * STG_H + (wn*64 + j*16) * LDH + kk*16], LDH);
#pragma unroll
            for (int i = 0; i < 2; i++)
#pragma unroll
                for (int j = 0; j < 4; j++)
                    wmma::mma_sync(acc[i][j], af[i], bf[j], acc[i][j]);
        }
    }
#pragma unroll
    for (int i = 0; i < 2; i++)
#pragma unroll
        for (int j = 0; j < 4; j++)
            wmma::store_matrix_sync(C + (size_t)(m0 + wm*32 + i*16) * N + n0 + wn*64 + j*16,
                                    acc[i][j], N, wmma::mem_row_major);
}

// ---------------- selection helpers ----------------
__device__ __forceinline__ float sel16f(const float* v, int i) {
    return (i & 8) ? ((i & 4) ? ((i & 2) ? ((i & 1) ? v[15] : v[14]) : ((i & 1) ? v[13] : v[12]))
                              : ((i & 2) ? ((i & 1) ? v[11] : v[10]) : ((i & 1) ? v[9]  : v[8])))
                   : ((i & 4) ? ((i & 2) ? ((i & 1) ? v[7]  : v[6])  : ((i & 1) ? v[5]  : v[4]))
                              : ((i & 2) ? ((i & 1) ? v[3]  : v[2])  : ((i & 1) ? v[1]  : v[0])));
}
__device__ __forceinline__ int sel16i(const int* v, int i) {
    return (i & 8) ? ((i & 4) ? ((i & 2) ? ((i & 1) ? v[15] : v[14]) : ((i & 1) ? v[13] : v[12]))
                              : ((i & 2) ? ((i & 1) ? v[11] : v[10]) : ((i & 1) ? v[9]  : v[8])))
                   : ((i & 4) ? ((i & 2) ? ((i & 1) ? v[7]  : v[6])  : ((i & 1) ? v[5]  : v[4]))
                              : ((i & 2) ? ((i & 1) ? v[3]  : v[2])  : ((i & 1) ? v[1]  : v[0])));
}

// ---------------- linear-domain Sinkhorn + argmax ----------------
__device__ __forceinline__ void sinkhorn_argmax_lin(float* p, int* idx) {
#pragma unroll
    for (int it = 0; it < 5; it++) {
#pragma unroll
        for (int i = 0; i < 4; i++) {
            float s = p[i*4] + p[i*4+1] + p[i*4+2] + p[i*4+3];
            float r = __fdividef(1.0f, s);
            p[i*4] *= r; p[i*4+1] *= r; p[i*4+2] *= r; p[i*4+3] *= r;
        }
        if (it < 4) {
#pragma unroll
            for (int j = 0; j < 4; j++) {
                float s = p[j] + p[4+j] + p[8+j] + p[12+j];
                float r = __fdividef(1.0f, s);
                p[j] *= r; p[4+j] *= r; p[8+j] *= r; p[12+j] *= r;
            }
        }
    }
#pragma unroll
    for (int j = 0; j < 4; j++) {
        int bi = 0; float bv = p[j];
        if (p[4+j]  > bv) { bv = p[4+j];  bi = 1; }
        if (p[8+j]  > bv) { bv = p[8+j];  bi = 2; }
        if (p[12+j] > bv) { bv = p[12+j]; bi = 3; }
        idx[j] = bi;
    }
}

__global__ void factor_kernel(const float* __restrict__ mask) {
    int tok = blockIdx.x * blockDim.x + threadIdx.x;
    if (tok >= NTOK) return;
    const float* so = g_small + (size_t)tok * NSMALL;
    int idxR[16], idxL[16];
    float a[16];
#pragma unroll
    for (int r = 0; r < 4; r++) {
#pragma unroll
        for (int e = 0; e < 16; e++) a[e] = __expf(so[r*16+e] * 2.0f);   // /TAU
        int id[4]; sinkhorn_argmax_lin(a, id);
#pragma unroll
        for (int j = 0; j < 4; j++) idxR[r*4+j] = id[j];
    }
#pragma unroll
    for (int r = 0; r < 4; r++) {
#pragma unroll
        for (int e = 0; e < 16; e++) a[e] = __expf(so[64+r*16+e] * 2.0f);
        int id[4]; sinkhorn_argmax_lin(a, id);
#pragma unroll
        for (int j = 0; j < 4; j++) idxL[r*4+j] = id[j];
    }
    float dR[16], dL[16];
#pragma unroll
    for (int n = 0; n < 16; n++) {
        dR[n] = __fdividef(1.0f, 1.0f + __expf(-so[160+n])) * tanhf(so[128+n]);
        dL[n] = __fdividef(1.0f, 1.0f + __expf(-so[176+n])) * tanhf(so[144+n]);
    }
    float mk = mask[tok];
    unsigned long long tp = 0ull;
#pragma unroll
    for (int j = 0; j < 16; j++) {
        int r = j >> 2;
        int i1 = r*4 + idxR[j];
        int i2 = ((i1 & 3) << 2) | (i1 >> 2);
        int i3 = (i2 & ~3) + sel16i(idxL, i2);
        tp |= ((unsigned long long)i3) << (4*j);
        g_c[tok*16+j] = sel16f(dR, i1) * sel16f(dL, i3);
        g_b[tok*16+j] = so[192+j] * mk;
    }
    g_tpack[tok] = tp;
}

// ---------------- chunked monomial scan ----------------
__global__ void scanA_kernel() {
    int wl = threadIdx.x >> 5, lane = threadIdx.x & 31, l = lane & 15;
    int gw = blockIdx.x * 8 + wl;
    __shared__ float sb[8][16];
    float* S = sb[wl];
    int base = (gw >> 6) * SS + (gw & 63) * CHUNK;
    int T = l; float C = 1.0f, Bv = 0.0f;
    for (int s = 0; s < CHUNK; s++) {
        int tok = base + s;
        unsigned long long tp = g_tpack[tok];
        int tj = (int)((tp >> (4*l)) & 15ull);
        float cj = g_c[tok*16+l], bj = g_b[tok*16+l];
        int   tT = __shfl_sync(0xffffffffu, tj, T);
        float cT = __shfl_sync(0xffffffffu, cj, T);
        if (lane < 16) S[l] = bj;
        __syncwarp();
        if (lane < 16) atomicAdd(&S[tj], cj * Bv);
        __syncwarp();
        if (lane < 16) Bv = S[l];
        __syncwarp();
        T = tT; C *= cT;
    }
    if (lane < 16) { g_Cc[gw*16+l] = C; g_Bc[gw*16+l] = Bv; }
    unsigned long long tpk = 0ull;
    for (int j = 0; j < 16; j++) {
        int v = __shfl_sync(0xffffffffu, T, j);
        tpk |= ((unsigned long long)(v & 15)) << (4*j);
    }
    if (lane == 0) g_Tc[gw] = tpk;
}

__global__ void scanB_kernel() {
    int wl = threadIdx.x >> 5, lane = threadIdx.x & 31, l = lane & 15;
    __shared__ float sb[8][16];
    float* S = sb[wl];
    float h = 0.0f;
    for (int k = 0; k < NCHUNK; k++) {
        int cid = wl * NCHUNK + k;
        if (lane < 16) g_hstart[cid*16+l] = h;
        unsigned long long tp = g_Tc[cid];
        int tj = (int)((tp >> (4*l)) & 15ull);
        float cj = g_Cc[cid*16+l], bj = g_Bc[cid*16+l];
        if (lane < 16) S[l] = bj;
        __syncwarp();
        if (lane < 16) atomicAdd(&S[tj], cj * h);
        __syncwarp();
        if (lane < 16) h = S[l];
        __syncwarp();
    }
}

__global__ void scanC_kernel() {
    int wl = threadIdx.x >> 5, lane = threadIdx.x & 31, l = lane & 15;
    int gw = blockIdx.x * 8 + wl;
    __shared__ float sb[8][16];
    float* S = sb[wl];
    int base = (gw >> 6) * SS + (gw & 63) * CHUNK;
    float h = (lane < 16) ? g_hstart[gw*16+l] : 0.0f;
    for (int s = 0; s < CHUNK; s++) {
        int tok = base + s;
        unsigned long long tp = g_tpack[tok];
        int tj = (int)((tp >> (4*l)) & 15ull);
        float cj = g_c[tok*16+l], bj = g_b[tok*16+l];
        if (lane < 16) S[l] = bj;
        __syncwarp();
        if (lane < 16) atomicAdd(&S[tj], cj * h);
        __syncwarp();
        if (lane < 16) { h = S[l]; g_hs[tok*16+l] = h; }
        __syncwarp();
    }
}

// ---------------- fused output: y = sigmoid(glogit) * (hs . W_C^T), block RMS ----------------
// y kept register-resident (16 tokens x 4 consecutive d per thread) -> single write pass.
__global__ void __launch_bounds__(256) out_kernel(const float* __restrict__ WC,
                                                  const float* __restrict__ norm_w,
                                                  float* __restrict__ out) {
    __shared__ float sHS[16][17];
    __shared__ float ssum[16];
    const int tid = threadIdx.x;
    const int tok0 = blockIdx.x * 16;
    const int d0 = tid * 4;

    float4 wc4[4][4];
#pragma unroll
    for (int q = 0; q < 4; q++) {
        const float4* wr = (const float4*)(WC + (size_t)(d0 + q) * 16);
#pragma unroll
        for (int p = 0; p < 4; p++) wc4[q][p] = wr[p];
    }
    sHS[tid >> 4][tid & 15] = g_hs[(size_t)(tok0 + (tid >> 4)) * 16 + (tid & 15)];
    if (tid < 16) ssum[tid] = 0.0f;
    __syncthreads();

    float4 yv[16];   // register-resident outputs
#pragma unroll
    for (int t = 0; t < 16; t++) {
        float hsr[16];
#pragma unroll
        for (int n = 0; n < 16; n++) hsr[n] = sHS[t][n];
        size_t off4 = ((size_t)(tok0 + t) * 1024 + d0) >> 2;
        float4 gl4 = ((const float4*)g_glogit)[off4];
        float glv[4] = {gl4.x, gl4.y, gl4.z, gl4.w};
        float* yp = (float*)&yv[t];
        float local = 0.0f;
#pragma unroll
        for (int q = 0; q < 4; q++) {
            float gate = __fdividef(1.0f, 1.0f + __expf(-glv[q]));
            float acc = 0.0f;
#pragma unroll
            for (int p = 0; p < 4; p++) {
                acc = fmaf(hsr[p*4+0], wc4[q][p].x, acc);
                acc = fmaf(hsr[p*4+1], wc4[q][p].y, acc);
                acc = fmaf(hsr[p*4+2], wc4[q][p].z, acc);
                acc = fmaf(hsr[p*4+3], wc4[q][p].w, acc);
            }
            float y = gate * acc;
            yp[q] = y;
            local = fmaf(y, y, local);
        }
        local += __shfl_down_sync(0xffffffffu, local, 16);
        local += __shfl_down_sync(0xffffffffu, local, 8);
        local += __shfl_down_sync(0xffffffffu, local, 4);
        local += __shfl_down_sync(0xffffffffu, local, 2);
        local += __shfl_down_sync(0xffffffffu, local, 1);
        if ((tid & 31) == 0) atomicAdd(&ssum[t], local);
    }
    __syncthreads();

    float4 nw4 = ((const float4*)norm_w)[tid];
#pragma unroll
    for (int t = 0; t < 16; t++) {
        float inv = rsqrtf(ssum[t] * (1.0f / 1024.0f) + 1e-6f);
        size_t off4 = ((size_t)(tok0 + t) * 1024 + d0) >> 2;
        float4 v = yv[t];
        v.x *= inv * nw4.x; v.y *= inv * nw4.y;
        v.z *= inv * nw4.z; v.w *= inv * nw4.w;
        ((float4*)out)[off4] = v;
    }
}

// ---------------- launch ----------------
extern "C" void kernel_launch(void* const* d_in, const int* in_sizes, int n_in,
                              void* d_out, int out_size) {
    const float* x    = (const float*)d_in[0];
    const float* mask = (const float*)d_in[1];
    const float* wpr  = (const float*)d_in[2];
    const float* wdr  = (const float*)d_in[3];
    const float* war  = (const float*)d_in[4];
    const float* wpl  = (const float*)d_in[5];
    const float* wdl  = (const float*)d_in[6];
    const float* wal  = (const float*)d_in[7];
    const float* wb   = (const float*)d_in[8];
    const float* wc   = (const float*)d_in[9];
    const float* wg   = (const float*)d_in[10];
    const float* nw   = (const float*)d_in[11];
    float* out = (float*)d_out;

    cudaFuncSetAttribute(gemm_kernel, cudaFuncAttributeMaxDynamicSharedMemorySize, GEMM_SMEM);

    __half *xhi, *xlo, *wsm, *wgt; float *sm, *gl;
    cudaGetSymbolAddress((void**)&xhi, g_xhi);
    cudaGetSymbolAddress((void**)&xlo, g_xlo);
    cudaGetSymbolAddress((void**)&wsm, g_wsmall);
    cudaGetSymbolAddress((void**)&wgt, g_wgate);
    cudaGetSymbolAddress((void**)&sm,  g_small);
    cudaGetSymbolAddress((void**)&gl,  g_glogit);

    convert_x_kernel<<<NTOK * DD / 4 / 256, 256>>>(x);
    convert_wsmall_kernel<<<NSMALL * KSPLIT / 256, 256>>>(wpr, wdr, war, wpl, wdl, wal, wb);
    convert_wgate_kernel<<<DD * DD / 256, 256>>>(wg);

    dim3 gall(10, NTOK / 128);   // bx 0-1: small GEMM; bx 2-9: gate GEMM
    gemm_kernel<<<gall, 256, GEMM_SMEM>>>(xhi, xlo, wsm, wgt, sm, gl);

    factor_kernel<<<NTOK / 256, 256>>>(mask);
    scanA_kernel<<<TOTCHUNK / 8, 256>>>();
    scanB_kernel<<<1, 256>>>();
    scanC_kernel<<<TOTCHUNK / 8, 256>>>();

    out_kernel<<<NTOK / 16, 256>>>(wc, nw, out);
}